// round 15
// baseline (speedup 1.0000x reference)
#include <cuda_runtime.h>
#include <cuda_bf16.h>

#define BT 16
#define BATCH 2
#define TT 8
#define CCH 128
#define SP 4096            // 64*64
#define PLANE (CCH*SP)     // 524288

#define L0 2048
#define D0 1024
#define L1 512
#define D1 4096
#define NS1 4              // split-K for scale1 scores

#define PADC 40
#define TILE_E (128*PADC)          // 5120 elements per matrix tile
#define TILE_B (TILE_E*2)          // 10240 bytes
#define STAGE_E (4*TILE_E)         // 20480 elements per stage
#define STAGE_B (4*TILE_B)         // 40960 bytes per stage
#define GEMM_SMEM (2*STAGE_B)      // 81920 bytes dynamic

// ---------------- scratch (static device memory; no allocation) ----------------
static __device__ float g_v[BT*PLANE];
static __device__ float g_depth[BT*64*64];
static __device__ float g_S0[BATCH*L0*L0];
static __device__ float g_S1p[NS1*BATCH*L1*L1];
static __device__ float g_mask0[BATCH*L0];
static __device__ float g_mask1[BATCH*L1];
static __device__ float g_sig0[BATCH*3*L0];
static __device__ float g_sig1[BATCH*3*L1];

// bf16 hi/lo operand buffers for tensor-core GEMMs
static __device__ __nv_bfloat16 g_Q0h[BATCH*L0*D0], g_Q0l[BATCH*L0*D0];
static __device__ __nv_bfloat16 g_K0h[BATCH*L0*D0], g_K0l[BATCH*L0*D0];
static __device__ __nv_bfloat16 g_Vt0h[BATCH*D0*L0], g_Vt0l[BATCH*D0*L0];
static __device__ __nv_bfloat16 g_Q1h[BATCH*L1*D1], g_Q1l[BATCH*L1*D1];
static __device__ __nv_bfloat16 g_K1h[BATCH*L1*D1], g_K1l[BATCH*L1*D1];
static __device__ __nv_bfloat16 g_Vt1h[BATCH*D1*L1], g_Vt1l[BATCH*D1*L1];
static __device__ __nv_bfloat16 g_P0h[BATCH*L0*L0], g_P0l[BATCH*L0*L0];
static __device__ __nv_bfloat16 g_P1h[BATCH*L1*L1], g_P1l[BATCH*L1*L1];
// attn output (pre-wo-conv) in bf16 hi/lo planes
static __device__ __nv_bfloat16 g_attnh[BT*PLANE], g_attnl[BT*PLANE];
// wo + qkv weights in bf16 hi/lo
static __device__ __nv_bfloat16 g_woh[CCH*1152], g_wol[CCH*1152];
static __device__ __nv_bfloat16 g_wqh[CCH*CCH], g_wql[CCH*CCH];
static __device__ __nv_bfloat16 g_wkh[CCH*CCH], g_wkl[CCH*CCH];
static __device__ __nv_bfloat16 g_wvh[CCH*CCH], g_wvl[CCH*CCH];
// x transposed per image: [n][pos][in] bf16 hi/lo
static __device__ __nv_bfloat16 g_xTh[BT*PLANE], g_xTl[BT*PLANE];

__device__ __forceinline__ float sigmoidf_(float x){ return 1.f/(1.f+__expf(-x)); }
__device__ __forceinline__ void split_(float v, __nv_bfloat16* h, __nv_bfloat16* l, int i){
  __nv_bfloat16 hh = __float2bfloat16(v);
  h[i] = hh; l[i] = __float2bfloat16(v - __bfloat162float(hh));
}
// Packed hi/lo store of an adjacent pair (i must be even; dest 4B aligned).
__device__ __forceinline__ void store2_(__nv_bfloat16* H, __nv_bfloat16* L, int i,
                                        float v0, float v1){
  __nv_bfloat16 h0 = __float2bfloat16(v0), h1 = __float2bfloat16(v1);
  __nv_bfloat162 hh; hh.x = h0; hh.y = h1;
  *(__nv_bfloat162*)&H[i] = hh;
  __nv_bfloat162 ll;
  ll.x = __float2bfloat16(v0 - __bfloat162float(h0));
  ll.y = __float2bfloat16(v1 - __bfloat162float(h1));
  *(__nv_bfloat162*)&L[i] = ll;
}

// Fast exp on the FMA pipe: exp(x)=2^(x*log2e), x<=0. rel err ~7e-7.
__device__ __forceinline__ float fexp_(float x){
  float t = fmaxf(x * 1.4426950408889634f, -126.f);
  float fi = floorf(t);
  float f = t - fi;
  float p = 1.5252733804e-5f;
  p = fmaf(p, f, 1.5403530394e-4f);
  p = fmaf(p, f, 1.3333558146e-3f);
  p = fmaf(p, f, 9.6181291076e-3f);
  p = fmaf(p, f, 5.5504108664e-2f);
  p = fmaf(p, f, 2.4022650696e-1f);
  p = fmaf(p, f, 6.9314718056e-1f);
  p = fmaf(p, f, 1.0f);
  return __int_as_float(((int)fi + 127) << 23) * p;
}

// QK epilogue scatter of an adjacent pos pair (pos even -> same patch, idx,idx+1).
__device__ __forceinline__ void qk_scat2(int bb, int tt, int ch, int pos,
    float v0, float v1,
    __nv_bfloat16* H0, __nv_bfloat16* Lo0, __nv_bfloat16* H1, __nv_bfloat16* Lo1)
{
  int y = pos >> 6, x = pos & 63;
  if (ch < 64) {
    int idx = (bb*L0 + tt*256 + (y>>2)*16 + (x>>2))*D0 + ch*16 + (y&3)*4 + (x&3);
    store2_(H0, Lo0, idx, v0, v1);
  } else {
    int idx = (bb*L1 + tt*64 + (y>>3)*8 + (x>>3))*D1 + (ch-64)*64 + (y&7)*8 + (x&7);
    store2_(H1, Lo1, idx, v0, v1);
  }
}

// PV epilogue scatter of an adjacent feature pair (f even -> dst,dst+1).
__device__ __forceinline__ void pv_scat2(int b, int l, int f, float v0, float v1, int scale)
{
  int dst;
  if (!scale) {
    int ch = f >> 4, pr = f & 15, tt = l >> 8, lrr = l & 255;
    dst = ((b*TT+tt)*CCH + ch)*SP + ((lrr>>4)*4 + (pr>>2))*64 + (lrr&15)*4 + (pr&3);
  } else {
    int ch = f >> 6, pr = f & 63, tt = l >> 6, lrr = l & 63;
    dst = ((b*TT+tt)*CCH + 64 + ch)*SP + ((lrr>>3)*8 + (pr>>3))*64 + (lrr&7)*8 + (pr&7);
  }
  store2_(g_attnh, g_attnl, dst, v0, v1);
}

#define MMA_BF16(c, a, b)                                               \
  asm volatile(                                                         \
    "mma.sync.aligned.m16n8k16.row.col.f32.bf16.bf16.f32 "              \
    "{%0,%1,%2,%3}, {%4,%5,%6,%7}, {%8,%9}, {%0,%1,%2,%3};"             \
    : "+f"((c)[0]), "+f"((c)[1]), "+f"((c)[2]), "+f"((c)[3])            \
    : "r"((a)[0]), "r"((a)[1]), "r"((a)[2]), "r"((a)[3]),               \
      "r"((b)[0]), "r"((b)[1]))

#define CP16(dst, src) \
  asm volatile("cp.async.ca.shared.global [%0], [%1], 16;" :: "r"(dst), "l"(src))
#define CPCOMMIT() asm volatile("cp.async.commit_group;" ::: "memory")
#define CPWAIT0()  asm volatile("cp.async.wait_group 0;" ::: "memory")
#define CPWAIT1()  asm volatile("cp.async.wait_group 1;" ::: "memory")

// ---------------- 0a: x transpose -> bf16 hi/lo [n][pos][in] ----------------
__global__ void k_xprep(const float* __restrict__ x)
{
  __shared__ float t[32][33];
  int n = blockIdx.z;
  int pos0 = blockIdx.x*32, in0 = blockIdx.y*32;
  int tx = threadIdx.x & 31, ty = threadIdx.x >> 5;
  const float* xp = x + (size_t)n*PLANE;
  #pragma unroll
  for (int i = 0; i < 4; i++)
    t[ty+8*i][tx] = xp[(size_t)(in0+ty+8*i)*SP + pos0+tx];
  __syncthreads();
  #pragma unroll
  for (int i = 0; i < 4; i++) {
    int p = ty + 8*i;
    size_t o = (size_t)n*PLANE + (size_t)(pos0+p)*CCH + in0 + tx;
    split_(t[tx][p], g_xTh, g_xTl, (int)o);
  }
}

// ---------------- 0b: weights -> bf16 hi/lo ----------------
__global__ void k_wprep(const float* __restrict__ wo, const float* __restrict__ wq,
                        const float* __restrict__ wk, const float* __restrict__ wv)
{
  int idx = blockIdx.x*256 + threadIdx.x;
  if (idx < CCH*1152) { split_(wo[idx], g_woh, g_wol, idx); return; }
  int r = idx - CCH*1152;
  if (r < CCH*CCH)        split_(wq[r], g_wqh, g_wql, r);
  else if (r < 2*CCH*CCH) split_(wk[r-CCH*CCH], g_wkh, g_wkl, r-CCH*CCH);
  else if (r < 3*CCH*CCH) split_(wv[r-2*CCH*CCH], g_wvh, g_wvl, r-2*CCH*CCH);
}

// ---------------- 2: depthwise 3x3 vle conv added into V ----------------
__global__ void k_vle(const float* __restrict__ x,
                      const float* __restrict__ wvle, const float* __restrict__ bvle)
{
  int idx = blockIdx.x*blockDim.x + threadIdx.x;
  if (idx >= BT*PLANE) return;
  int p  = idx & (SP-1);
  int ch = (idx >> 12) & 127;
  int y  = p >> 6, xx = p & 63;
  const float* xp = x + (size_t)(idx - p);
  const float* wp = wvle + ch*9;
  float s = bvle[ch];
  #pragma unroll
  for (int ky = 0; ky < 3; ky++) {
    int iy = y + ky - 1; if ((unsigned)iy >= 64u) continue;
    #pragma unroll
    for (int kx = 0; kx < 3; kx++) {
      int ix = xx + kx - 1; if ((unsigned)ix >= 64u) continue;
      s += wp[ky*3+kx] * xp[iy*64+ix];
    }
  }
  g_v[idx] += s;
}

// ---------------- 3: fused depth conv ----------------
__global__ void __launch_bounds__(256) k_depth(
    const float* __restrict__ dm,
    const float* __restrict__ wd1, const float* __restrict__ bd1,
    const float* __restrict__ wd2, const float* __restrict__ bd2)
{
  __shared__ float sdep[67][68];
  __shared__ float sd1[4][33][34];
  __shared__ float w1s[CCH*9];
  __shared__ float w2s[CCH*9];
  __shared__ float b1s[CCH];
  int n = blockIdx.y;
  int TY = blockIdx.x >> 2, TX = blockIdx.x & 3;
  int tid = threadIdx.x;
  for (int i = tid; i < CCH*9; i += 256) { w1s[i] = wd1[i]; w2s[i] = wd2[i]; }
  for (int i = tid; i < CCH;   i += 256) b1s[i] = bd1[i];
  const float* dmp = dm + (size_t)n*65536;
  int gy0 = TY*64 - 3, gx0 = TX*64 - 3;
  for (int i = tid; i < 67*67; i += 256) {
    int r = i/67, c = i - r*67;
    int gy = gy0 + r, gx = gx0 + c;
    float v = 0.f;
    if ((unsigned)gy < 256u && (unsigned)gx < 256u) v = dmp[gy*256+gx];
    sdep[r][c] = v;
  }
  int oy = tid >> 4, ox = tid & 15;
  int d1r0 = TY*32 - 1, d1c0 = TX*32 - 1;
  float acc = bd2[0];
  __syncthreads();
  for (int c0 = 0; c0 < CCH; c0 += 4) {
    for (int i = tid; i < 4*33*33; i += 256) {
      int cc = i / 1089;
      int rr = i - cc*1089;
      int dr = rr / 33, dc = rr - dr*33;
      const float* wc = &w1s[(c0+cc)*9];
      float s = b1s[c0+cc];
      #pragma unroll
      for (int ky = 0; ky < 3; ky++)
        #pragma unroll
        for (int kx = 0; kx < 3; kx++)
          s += wc[ky*3+kx] * sdep[2*dr+ky][2*dc+kx];
      int gr = d1r0 + dr, gc = d1c0 + dc;
      s = ((unsigned)gr < 128u && (unsigned)gc < 128u) ? fmaxf(s, 0.f) : 0.f;
      sd1[cc][dr][dc] = s;
    }
    __syncthreads();
    #pragma unroll
    for (int cc = 0; cc < 4; cc++) {
      const float* wc = &w2s[(c0+cc)*9];
      #pragma unroll
      for (int ky = 0; ky < 3; ky++)
        #pragma unroll
        for (int kx = 0; kx < 3; kx++)
          acc += wc[ky*3+kx] * sd1[cc][2*oy+ky][2*ox+kx];
    }
    __syncthreads();
  }
  g_depth[(size_t)n*4096 + (TY*16+oy)*64 + TX*16+ox] = fmaxf(acc, 0.f);
}

// ---------------- 5b: patchify V transposed -> bf16 hi/lo, [b][d][l] ----------------
__global__ void k_patch_vt(int scale)
{
  int idx = blockIdx.x*256 + threadIdx.x;
  int L = scale? L1:L0, D = scale? D1:D0, PH = scale? 8:4, OH = scale? 8:16;
  if (idx >= 2*L*D) return;
  int b = idx / (L*D);
  int r = idx - b*L*D;
  int d = r / L;
  int l = r - d*L;
  int pp = PH*PH;
  int ch = d / pp;
  int pr = d - ch*pp;
  int py = pr / PH, px = pr - py*PH;
  int oo = OH*OH;
  int tt = l / oo;
  int lr2 = l - tt*oo;
  int oh = lr2 / OH, ow = lr2 - oh*OH;
  int src = ((b*TT+tt)*CCH + scale*64 + ch)*SP + (oh*PH+py)*64 + ow*PH + px;
  float v = g_v[src];
  __nv_bfloat16* Vh = scale? g_Vt1h : g_Vt0h;
  __nv_bfloat16* Vl = scale? g_Vt1l : g_Vt0l;
  split_(v, Vh, Vl, idx);
}

// ---------------- 6: per-patch mask + depth stats ----------------
__global__ void k_stats(const float* __restrict__ m, int scale)
{
  int L = scale? L1:L0, PH = scale? 8:4, OH = scale? 8:16;
  int HW = PH*PH, MED = (HW-1)/2;
  int idx = blockIdx.x*blockDim.x + threadIdx.x;
  if (idx >= 2*L) return;
  int b = idx / L, l = idx - b*L;
  int oo = OH*OH;
  int tt = l / oo;
  int lr = l - tt*oo;
  int oh = lr / OH, ow = lr - oh*OH;
  int y0 = oh*PH, x0 = ow*PH;
  const float* mp = m + (size_t)(b*TT+tt)*4096;
  float s = 0.f;
  for (int py = 0; py < PH; py++)
    for (int px = 0; px < PH; px++)
      s += mp[(y0+py)*64 + x0+px];
  (scale? g_mask1 : g_mask0)[idx] = (s/(float)HW > 0.5f) ? 1.f : 0.f;

  const float* dp = g_depth + (size_t)(b*TT+tt)*4096;
  float buf[64];
  for (int i = 0; i < HW; i++) {
    int py = i / PH, px = i - py*PH;
    buf[i] = dp[(y0+py)*64 + x0+px];
  }
  float mn = buf[0], mx = buf[0];
  for (int i = 1; i < HW; i++) { mn = fminf(mn, buf[i]); mx = fmaxf(mx, buf[i]); }
  float med = buf[0];
  for (int i = 0; i < HW; i++) {
    int cnt = 0;
    for (int j = 0; j < HW; j++)
      cnt += (buf[j] < buf[i]) || (buf[j] == buf[i] && j < i);
    if (cnt == MED) med = buf[i];
  }
  float* sg = (scale? g_sig1 : g_sig0) + (size_t)b*3*L;
  sg[l]       = sigmoidf_(med);
  sg[L + l]   = sigmoidf_(mx);
  sg[2*L + l] = sigmoidf_(mn);
}

// ---------------- 7: fused hi/lo NT GEMM, 128x128x32, double-buffered cp.async ----------------
// emode: 0 = dense fp32 out, 1 = QK patched scatter, 2/3 = PV unpatch scatter (scale0/1)
__global__ void __launch_bounds__(256,2) k_gemm_nt(int which, const float* __restrict__ bias)
{
  extern __shared__ __align__(16) __nv_bfloat16 smp[];
  const __nv_bfloat16 *Ah, *Al, *Bh, *Bl;
  float *Cd = nullptr, *Cp = nullptr;
  __nv_bfloat16 *H0 = nullptr, *Lo0 = nullptr, *H1 = nullptr, *Lo1 = nullptr;
  int M, N, K, ns, ashare = 0, emode = 0; float scl = 1.f;
  if (which == 0)      { Ah=g_Q0h; Al=g_Q0l; Bh=g_K0h;  Bl=g_K0l;  Cd=g_S0;
                         M=L0; N=L0; K=D0; ns=1; scl=0.03125f; }
  else if (which == 1) { Ah=g_Q1h; Al=g_Q1l; Bh=g_K1h;  Bl=g_K1l;  Cp=g_S1p;
                         M=L1; N=L1; K=D1; ns=NS1; }
  else if (which == 2) { Ah=g_P0h; Al=g_P0l; Bh=g_Vt0h; Bl=g_Vt0l;
                         M=L0; N=D0; K=L0; ns=1; emode=2; }
  else if (which == 3) { Ah=g_P1h; Al=g_P1l; Bh=g_Vt1h; Bl=g_Vt1l;
                         M=L1; N=D1; K=L1; ns=1; emode=3; }
  else if (which == 4) { Ah=g_wqh; Al=g_wql; Bh=g_xTh;  Bl=g_xTl;
                         M=CCH; N=SP; K=CCH; ns=1; ashare=1; emode=1;
                         H0=g_Q0h; Lo0=g_Q0l; H1=g_Q1h; Lo1=g_Q1l; }
  else if (which == 5) { Ah=g_wkh; Al=g_wkl; Bh=g_xTh;  Bl=g_xTl;
                         M=CCH; N=SP; K=CCH; ns=1; ashare=1; emode=1;
                         H0=g_K0h; Lo0=g_K0l; H1=g_K1h; Lo1=g_K1l; }
  else                 { Ah=g_wvh; Al=g_wvl; Bh=g_xTh;  Bl=g_xTl;  Cd=g_v;
                         M=CCH; N=SP; K=CCH; ns=1; ashare=1; }

  int z = blockIdx.z;
  int b = z / ns, sp = z - b*ns;
  int Kc = K / ns;
  size_t aoff = (ashare ? 0 : (size_t)b*M*K) + (size_t)sp*Kc;
  size_t boff = (size_t)b*N*K + (size_t)sp*Kc;
  int row0 = blockIdx.y*128, col0 = blockIdx.x*128;
  int tid = threadIdx.x, lane = tid&31, wid = tid>>5;
  int wm = (wid&1)*64, wn = (wid>>1)*32;
  int lr = tid>>1, lc8 = (tid&1)*16;
  const __nv_bfloat16* Ahp = Ah + aoff + (size_t)(row0+lr)*K + lc8;
  const __nv_bfloat16* Alp = Al + aoff + (size_t)(row0+lr)*K + lc8;
  const __nv_bfloat16* Bhp = Bh + boff + (size_t)(col0+lr)*K + lc8;
  const __nv_bfloat16* Blp = Bl + boff + (size_t)(col0+lr)*K + lc8;
  unsigned sbase = (unsigned)__cvta_generic_to_shared(smp);
  unsigned rofs = (unsigned)((lr*PADC + lc8)*2);   // 80B row stride -> 16B aligned
  float c[4][4][4] = {};
  int nkb = Kc/32;

  // prefetch k-block 0 into stage 0
  CP16(sbase + rofs,            Ahp);  CP16(sbase + rofs + 16,            Ahp + 8);
  CP16(sbase + TILE_B + rofs,   Alp);  CP16(sbase + TILE_B + rofs + 16,   Alp + 8);
  CP16(sbase + 2*TILE_B + rofs, Bhp);  CP16(sbase + 2*TILE_B + rofs + 16, Bhp + 8);
  CP16(sbase + 3*TILE_B + rofs, Blp);  CP16(sbase + 3*TILE_B + rofs + 16, Blp + 8);
  CPCOMMIT();

  for (int kb = 0; kb < nkb; kb++) {
    int cur = kb & 1;
    if (kb+1 < nkb) {
      unsigned st = sbase + (unsigned)((cur^1)*STAGE_B);
      int o = (kb+1)*32;
      CP16(st + rofs,            Ahp + o);  CP16(st + rofs + 16,            Ahp + o + 8);
      CP16(st + TILE_B + rofs,   Alp + o);  CP16(st + TILE_B + rofs + 16,   Alp + o + 8);
      CP16(st + 2*TILE_B + rofs, Bhp + o);  CP16(st + 2*TILE_B + rofs + 16, Bhp + o + 8);
      CP16(st + 3*TILE_B + rofs, Blp + o);  CP16(st + 3*TILE_B + rofs + 16, Blp + o + 8);
      CPCOMMIT();
      CPWAIT1();
    } else {
      CPWAIT0();
    }
    __syncthreads();
    const __nv_bfloat16* Ahs = smp + cur*STAGE_E;
    const __nv_bfloat16* Als = Ahs + TILE_E;
    const __nv_bfloat16* Bhs = Ahs + 2*TILE_E;
    const __nv_bfloat16* Bls = Ahs + 3*TILE_E;
    #pragma unroll
    for (int ks = 0; ks < 2; ks++) {
      int kk = ks*16 + (lane&3)*2;
      unsigned af[4][4], bfh[4][2], bfl[4][2];
      #pragma unroll
      for (int mi = 0; mi < 4; mi++) {
        int r = wm + mi*16 + (lane>>2);
        af[mi][0] = *(const unsigned*)&Ahs[r*PADC + kk];
        af[mi][1] = *(const unsigned*)&Ahs[(r+8)*PADC + kk];
        af[mi][2] = *(const unsigned*)&Ahs[r*PADC + kk+8];
        af[mi][3] = *(const unsigned*)&Ahs[(r+8)*PADC + kk+8];
      }
      #pragma unroll
      for (int ni = 0; ni < 4; ni++) {
        int nn = wn + ni*8 + (lane>>2);
        bfh[ni][0] = *(const unsigned*)&Bhs[nn*PADC + kk];
        bfh[ni][1] = *(const unsigned*)&Bhs[nn*PADC + kk+8];
        bfl[ni][0] = *(const unsigned*)&Bls[nn*PADC + kk];
        bfl[ni][1] = *(const unsigned*)&Bls[nn*PADC + kk+8];
      }
      #pragma unroll
      for (int mi = 0; mi < 4; mi++)
        #pragma unroll
        for (int ni = 0; ni < 4; ni++) {
          MMA_BF16(c[mi][ni], af[mi], bfh[ni]);
          MMA_BF16(c[mi][ni], af[mi], bfl[ni]);
        }
      #pragma unroll
      for (int mi = 0; mi < 4; mi++) {
        int r = wm + mi*16 + (lane>>2);
        af[mi][0] = *(const unsigned*)&Als[r*PADC + kk];
        af[mi][1] = *(const unsigned*)&Als[(r+8)*PADC + kk];
        af[mi][2] = *(const unsigned*)&Als[r*PADC + kk+8];
        af[mi][3] = *(const unsigned*)&Als[(r+8)*PADC + kk+8];
      }
      #pragma unroll
      for (int mi = 0; mi < 4; mi++)
        #pragma unroll
        for (int ni = 0; ni < 4; ni++)
          MMA_BF16(c[mi][ni], af[mi], bfh[ni]);
    }
    __syncthreads();
  }

  if (emode == 0) {
    float* Co;
    if (ns > 1) Co = Cp + ((size_t)sp*BATCH + b)*M*N;
    else        Co = Cd + (size_t)b*M*N;
    #pragma unroll
    for (int mi = 0; mi < 4; mi++) {
      int r = row0 + wm + mi*16 + (lane>>2);
      float b0 = bias ? bias[r]   : 0.f;
      float b1 = bias ? bias[r+8] : 0.f;
      #pragma unroll
      for (int ni = 0; ni < 4; ni++) {
        int cc = col0 + wn + ni*8 + (lane&3)*2;
        float2 v0 = make_float2(c[mi][ni][0]*scl + b0, c[mi][ni][1]*scl + b0);
        float2 v1 = make_float2(c[mi][ni][2]*scl + b1, c[mi][ni][3]*scl + b1);
        *(float2*)&Co[(size_t)r*N + cc]     = v0;
        *(float2*)&Co[(size_t)(r+8)*N + cc] = v1;
      }
    }
  } else if (emode == 1) {
    // QK scatter: z = image index; rows = channel, cols = spatial pos (packed pairs)
    int bb = z >> 3, tt = z & 7;
    #pragma unroll
    for (int mi = 0; mi < 4; mi++) {
      int r = wm + mi*16 + (lane>>2);
      float b0 = bias[r], b1 = bias[r+8];
      #pragma unroll
      for (int ni = 0; ni < 4; ni++) {
        int cc = col0 + wn + ni*8 + (lane&3)*2;
        qk_scat2(bb, tt, r,   cc, c[mi][ni][0] + b0, c[mi][ni][1] + b0, H0, Lo0, H1, Lo1);
        qk_scat2(bb, tt, r+8, cc, c[mi][ni][2] + b1, c[mi][ni][3] + b1, H0, Lo0, H1, Lo1);
      }
    }
  } else {
    // PV unpatch scatter: z = batch; rows = token l, cols = feature f (packed pairs)
    int sc1 = (emode == 3);
    #pragma unroll
    for (int mi = 0; mi < 4; mi++) {
      int r = row0 + wm + mi*16 + (lane>>2);
      #pragma unroll
      for (int ni = 0; ni < 4; ni++) {
        int cc = col0 + wn + ni*8 + (lane&3)*2;
        pv_scat2(b, r,   cc, c[mi][ni][0], c[mi][ni][1], sc1);
        pv_scat2(b, r+8, cc, c[mi][ni][2], c[mi][ni][3], sc1);
      }
    }
  }
}

// ---------------- 9: fused 3-head masked softmax (fast exp; scale1 sums split-K partials) ----------------
__device__ __forceinline__ float warp_max_(float v){
  #pragma unroll
  for (int o = 16; o; o >>= 1) v = fmaxf(v, __shfl_xor_sync(0xffffffffu, v, o));
  return v;
}
__device__ __forceinline__ float warp_sum_(float v){
  #pragma unroll
  for (int o = 16; o; o >>= 1) v += __shfl_xor_sync(0xffffffffu, v, o);
  return v;
}

__global__ void k_softmax(int scale)
{
  extern __shared__ float sv[];      // 3*L
  __shared__ float rbuf[3][8];
  int L = scale? L1:L0;
  const float* mk = (scale? g_mask1 : g_mask0) + (size_t)blockIdx.y*L;
  const float* sg = (scale? g_sig1  : g_sig0)  + (size_t)blockIdx.y*3*L;
  size_t rowoff = ((size_t)blockIdx.y*L + blockIdx.x)*L;
  const float* row0p = g_S0 + rowoff;
  const float* p1 = g_S1p + (size_t)blockIdx.y*L1*L1 + (size_t)blockIdx.x*L1;
  const size_t PS = (size_t)BATCH*L1*L1;
  __nv_bfloat16* Ph = scale? g_P1h : g_P0h;
  __nv_bfloat16* Pl = scale? g_P1l : g_P0l;
  int tid = threadIdx.x, lane = tid&31, wid = tid>>5;

  float m0 = -3e38f, m1 = -3e38f, m2 = -3e38f;
  for (int k = tid; k < L; k += 256) {
    float s;
    if (scale) s = (p1[k] + p1[k+PS] + p1[k+2*PS] + p1[k+3*PS]) * 0.015625f;
    else       s = row0p[k];
    float v0, v1, v2;
    if (mk[k] > 0.5f) { v0 = v1 = v2 = -1e9f; }
    else { v0 = s*sg[k]; v1 = s*sg[L+k]; v2 = s*sg[2*L+k]; }
    sv[k] = v0; sv[L+k] = v1; sv[2*L+k] = v2;
    m0 = fmaxf(m0, v0); m1 = fmaxf(m1, v1); m2 = fmaxf(m2, v2);
  }
  m0 = warp_max_(m0); m1 = warp_max_(m1); m2 = warp_max_(m2);
  if (lane == 0) { rbuf[0][wid]=m0; rbuf[1][wid]=m1; rbuf[2][wid]=m2; }
  __syncthreads();
  m0 = rbuf[0][0]; m1 = rbuf[1][0]; m2 = rbuf[2][0];
  #pragma unroll
  for (int w = 1; w < 8; w++) {
    m0 = fmaxf(m0, rbuf[0][w]); m1 = fmaxf(m1, rbuf[1][w]); m2 = fmaxf(m2, rbuf[2][w]);
  }
  __syncthreads();

  float z0 = 0.f, z1 = 0.f, z2 = 0.f;
  for (int k = tid; k < L; k += 256) {
    float e0 = fexp_(sv[k]     - m0);
    float e1 = fexp_(sv[L+k]   - m1);
    float e2 = fexp_(sv[2*L+k] - m2);
    sv[k] = e0; sv[L+k] = e1; sv[2*L+k] = e2;
    z0 += e0; z1 += e1; z2 += e2;
  }
  z0 = warp_sum_(z0); z1 = warp_sum_(z1); z2 = warp_sum_(z2);
  if (lane == 0) { rbuf[0][wid]=z0; rbuf[1][wid]=z1; rbuf[2][wid]=z2; }
  __syncthreads();
  z0 = 0.f; z1 = 0.f; z2 = 0.f;
  #pragma unroll
  for (int w = 0; w < 8; w++) { z0 += rbuf[0][w]; z1 += rbuf[1][w]; z2 += rbuf[2][w]; }
  float i0 = 1.f/(3.f*z0), i1 = 1.f/(3.f*z1), i2 = 1.f/(3.f*z2);
  for (int k = tid; k < L; k += 256) {
    float p = sv[k]*i0 + sv[L+k]*i1 + sv[2*L+k]*i2;
    split_(p, Ph, Pl, (int)(rowoff + k));
  }
}

// ---------------- 12: wo 3x3 conv, single-pass fused hi/lo implicit GEMM ----------------
__global__ void __launch_bounds__(256) k_conv_mma(
    const float* __restrict__ bo, float* __restrict__ out)
{
  __shared__ __align__(16) __nv_bfloat16 Ahs[128][40];
  __shared__ __align__(16) __nv_bfloat16 Als[128][40];
  __shared__ __align__(16) __nv_bfloat16 Bhs[128][40];
  __shared__ __align__(16) __nv_bfloat16 Bls[128][40];
  int n = blockIdx.z;
  int col0 = blockIdx.x*128;
  int tid = threadIdx.x, lane = tid&31, wid = tid>>5;
  int wm = (wid&1)*64, wn = (wid>>1)*32;
  int lr = tid>>1, lc = (tid&1)*16;
  int nloc = tid & 127, khalf = tid >> 7;
  int pos = col0 + nloc;
  int py = pos >> 6, px = pos & 63;
  const __nv_bfloat16* Bph = g_attnh + (size_t)n*PLANE;
  const __nv_bfloat16* Bpl = g_attnl + (size_t)n*PLANE;
  float c[4][4][4] = {};
  #pragma unroll 1
  for (int kb = 0; kb < 36; kb++) {
    __syncthreads();
    *(float4*)&Ahs[lr][lc]   = *(const float4*)(g_woh + (size_t)lr*1152 + kb*32 + lc);
    *(float4*)&Ahs[lr][lc+8] = *(const float4*)(g_woh + (size_t)lr*1152 + kb*32 + lc + 8);
    *(float4*)&Als[lr][lc]   = *(const float4*)(g_wol + (size_t)lr*1152 + kb*32 + lc);
    *(float4*)&Als[lr][lc+8] = *(const float4*)(g_wol + (size_t)lr*1152 + kb*32 + lc + 8);
    #pragma unroll
    for (int u = 0; u < 16; u++) {
      int k = kb*32 + khalf*16 + u;
      int ic = k/9;
      int rr = k - ic*9;
      int ky = rr/3 - 1, kx = rr - (rr/3)*3 - 1;
      int iy = py + ky, ix = px + kx;
      __nv_bfloat16 vh = __float2bfloat16(0.f), vl = vh;
      if ((unsigned)iy < 64u && (unsigned)ix < 64u) {
        size_t o = (size_t)ic*SP + iy*64 + ix;
        vh = Bph[o]; vl = Bpl[o];
      }
      Bhs[nloc][khalf*16 + u] = vh;
      Bls[nloc][khalf*16 + u] = vl;
    }
    __syncthreads();
    #pragma unroll
    for (int ks = 0; ks < 2; ks++) {
      int kk = ks*16 + (lane&3)*2;
      unsigned af[4][4], bfh[4][2], bfl[4][2];
      #pragma unroll
      for (int mi = 0; mi < 4; mi++) {
        int r = wm + mi*16 + (lane>>2);
        af[mi][0] = *(const unsigned*)&Ahs[r][kk];
        af[mi][1] = *(const unsigned*)&Ahs[r+8][kk];
        af[mi][2] = *(const unsigned*)&Ahs[r][kk+8];
        af[mi][3] = *(const unsigned*)&Ahs[r+8][kk+8];
      }
      #pragma unroll
      for (int ni = 0; ni < 4; ni++) {
        int nn = wn + ni*8 + (lane>>2);
        bfh[ni][0] = *(const unsigned*)&Bhs[nn][kk];
        bfh[ni][1] = *(const unsigned*)&Bhs[nn][kk+8];
        bfl[ni][0] = *(const unsigned*)&Bls[nn][kk];
        bfl[ni][1] = *(const unsigned*)&Bls[nn][kk+8];
      }
      #pragma unroll
      for (int mi = 0; mi < 4; mi++)
        #pragma unroll
        for (int ni = 0; ni < 4; ni++) {
          MMA_BF16(c[mi][ni], af[mi], bfh[ni]);
          MMA_BF16(c[mi][ni], af[mi], bfl[ni]);
        }
      #pragma unroll
      for (int mi = 0; mi < 4; mi++) {
        int r = wm + mi*16 + (lane>>2);
        af[mi][0] = *(const unsigned*)&Als[r][kk];
        af[mi][1] = *(const unsigned*)&Als[r+8][kk];
        af[mi][2] = *(const unsigned*)&Als[r][kk+8];
        af[mi][3] = *(const unsigned*)&Als[r+8][kk+8];
      }
      #pragma unroll
      for (int mi = 0; mi < 4; mi++)
        #pragma unroll
        for (int ni = 0; ni < 4; ni++)
          MMA_BF16(c[mi][ni], af[mi], bfh[ni]);
    }
  }
  #pragma unroll
  for (int mi = 0; mi < 4; mi++) {
    int r = wm + mi*16 + (lane>>2);
    float b0 = bo[r], b1 = bo[r+8];
    #pragma unroll
    for (int ni = 0; ni < 4; ni++) {
      int cc = col0 + wn + ni*8 + (lane&3)*2;
      float v0 = c[mi][ni][0] + b0, v1 = c[mi][ni][1] + b0;
      float v2 = c[mi][ni][2] + b1, v3 = c[mi][ni][3] + b1;
      v0 = (v0 >= 0.f) ? v0 : 0.2f*v0;
      v1 = (v1 >= 0.f) ? v1 : 0.2f*v1;
      v2 = (v2 >= 0.f) ? v2 : 0.2f*v2;
      v3 = (v3 >= 0.f) ? v3 : 0.2f*v3;
      *(float2*)&out[(size_t)n*PLANE + (size_t)r*SP + cc]     = make_float2(v0, v1);
      *(float2*)&out[(size_t)n*PLANE + (size_t)(r+8)*SP + cc] = make_float2(v2, v3);
    }
  }
}

// ---------------- host ----------------
extern "C" void kernel_launch(void* const* d_in, const int* in_sizes, int n_in,
                              void* d_out, int out_size)
{
  const float* x     = (const float*)d_in[0];
  const float* m     = (const float*)d_in[1];
  const float* dmap  = (const float*)d_in[2];
  const float* wq    = (const float*)d_in[3];
  const float* bq    = (const float*)d_in[4];
  const float* wk    = (const float*)d_in[5];
  const float* bk    = (const float*)d_in[6];
  const float* wv    = (const float*)d_in[7];
  const float* bv    = (const float*)d_in[8];
  const float* wvle  = (const float*)d_in[9];
  const float* bvle  = (const float*)d_in[10];
  const float* wd1   = (const float*)d_in[11];
  const float* bd1   = (const float*)d_in[12];
  const float* wd2   = (const float*)d_in[13];
  const float* bd2   = (const float*)d_in[14];
  const float* wo    = (const float*)d_in[15];
  const float* bo    = (const float*)d_in[16];
  float* out = (float*)d_out;

  cudaFuncSetAttribute(k_gemm_nt, cudaFuncAttributeMaxDynamicSharedMemorySize, GEMM_SMEM);

  k_xprep<<<dim3(128,4,16), 256>>>(x);
  k_wprep<<<(CCH*1152 + 3*CCH*CCH + 255)/256, 256>>>(wo, wq, wk, wv);

  // QKV: Q/K scatter directly to patched bf16 hi/lo; V dense (vle adds next)
  k_gemm_nt<<<dim3(SP/128, 1, BT), 256, GEMM_SMEM>>>(4, bq);
  k_gemm_nt<<<dim3(SP/128, 1, BT), 256, GEMM_SMEM>>>(5, bk);
  k_gemm_nt<<<dim3(SP/128, 1, BT), 256, GEMM_SMEM>>>(6, bv);

  k_vle<<<(BT*PLANE)/256, 256>>>(x, wvle, bvle);
  k_depth<<<dim3(16,16), 256>>>(dmap, wd1, bd1, wd2, bd2);

  k_patch_vt<<<(2*L0*D0)/256, 256>>>(0);
  k_patch_vt<<<(2*L1*D1)/256, 256>>>(1);
  k_stats<<<(2*L0+255)/256, 256>>>(m, 0);
  k_stats<<<(2*L1+255)/256, 256>>>(m, 1);

  k_gemm_nt<<<dim3(L0/128, L0/128, BATCH), 256, GEMM_SMEM>>>(0, nullptr);
  k_gemm_nt<<<dim3(L1/128, L1/128, BATCH*NS1), 256, GEMM_SMEM>>>(1, nullptr);

  k_softmax<<<dim3(L0, BATCH), 256, 3*L0*sizeof(float)>>>(0);
  k_softmax<<<dim3(L1, BATCH), 256, 3*L1*sizeof(float)>>>(1);

  // PV: scatter directly into attn planes (no Y buffers, no unpatch)
  k_gemm_nt<<<dim3(D0/128, L0/128, BATCH), 256, GEMM_SMEM>>>(2, nullptr);
  k_gemm_nt<<<dim3(D1/128, L1/128, BATCH), 256, GEMM_SMEM>>>(3, nullptr);

  k_conv_mma<<<dim3(32,1,16), 256>>>(bo, out);

  cudaMemcpyAsync(out + BT*PLANE, dmap, (size_t)BT*65536*sizeof(float),
                  cudaMemcpyDeviceToDevice);
}

// round 16
// speedup vs baseline: 1.5438x; 1.5438x over previous
#include <cuda_runtime.h>
#include <cuda_bf16.h>

#define BT 16
#define BATCH 2
#define TT 8
#define CCH 128
#define SP 4096            // 64*64
#define PLANE (CCH*SP)     // 524288

#define L0 2048
#define D0 1024
#define L1 512
#define D1 4096
#define NS1 4              // split-K for scale1 scores

#define PADC 40
#define TILE_E (128*PADC)          // 5120 elements per matrix tile
#define TILE_B (TILE_E*2)          // 10240 bytes
#define STAGE_E (4*TILE_E)         // 20480 elements per stage
#define STAGE_B (4*TILE_B)         // 40960 bytes per stage
#define GEMM_SMEM (2*STAGE_B)      // 81920 bytes dynamic

// ---------------- scratch (static device memory; no allocation) ----------------
static __device__ float g_v[BT*PLANE];
static __device__ float g_depth[BT*64*64];
static __device__ float g_S0[BATCH*L0*L0];
static __device__ float g_S1p[NS1*BATCH*L1*L1];
static __device__ float g_mask0[BATCH*L0];
static __device__ float g_mask1[BATCH*L1];
static __device__ float g_sig0[BATCH*3*L0];
static __device__ float g_sig1[BATCH*3*L1];

// bf16 hi/lo operand buffers for tensor-core GEMMs
static __device__ __nv_bfloat16 g_Q0h[BATCH*L0*D0], g_Q0l[BATCH*L0*D0];
static __device__ __nv_bfloat16 g_K0h[BATCH*L0*D0], g_K0l[BATCH*L0*D0];
static __device__ __nv_bfloat16 g_Vt0h[BATCH*D0*L0], g_Vt0l[BATCH*D0*L0];
static __device__ __nv_bfloat16 g_Q1h[BATCH*L1*D1], g_Q1l[BATCH*L1*D1];
static __device__ __nv_bfloat16 g_K1h[BATCH*L1*D1], g_K1l[BATCH*L1*D1];
static __device__ __nv_bfloat16 g_Vt1h[BATCH*D1*L1], g_Vt1l[BATCH*D1*L1];
static __device__ __nv_bfloat16 g_P0h[BATCH*L0*L0], g_P0l[BATCH*L0*L0];
static __device__ __nv_bfloat16 g_P1h[BATCH*L1*L1], g_P1l[BATCH*L1*L1];
// attn output (pre-wo-conv) in bf16 hi/lo planes
static __device__ __nv_bfloat16 g_attnh[BT*PLANE], g_attnl[BT*PLANE];
// wo + qkv weights in bf16 hi/lo
static __device__ __nv_bfloat16 g_woh[CCH*1152], g_wol[CCH*1152];
static __device__ __nv_bfloat16 g_wqh[CCH*CCH], g_wql[CCH*CCH];
static __device__ __nv_bfloat16 g_wkh[CCH*CCH], g_wkl[CCH*CCH];
static __device__ __nv_bfloat16 g_wvh[CCH*CCH], g_wvl[CCH*CCH];
// x transposed per image: [n][pos][in] bf16 hi/lo
static __device__ __nv_bfloat16 g_xTh[BT*PLANE], g_xTl[BT*PLANE];

__device__ __forceinline__ float sigmoidf_(float x){ return 1.f/(1.f+__expf(-x)); }
__device__ __forceinline__ void split_(float v, __nv_bfloat16* h, __nv_bfloat16* l, int i){
  __nv_bfloat16 hh = __float2bfloat16(v);
  h[i] = hh; l[i] = __float2bfloat16(v - __bfloat162float(hh));
}
// Packed hi/lo store of an adjacent pair (i must be even; dest 4B aligned).
__device__ __forceinline__ void store2_(__nv_bfloat16* H, __nv_bfloat16* L, int i,
                                        float v0, float v1){
  __nv_bfloat16 h0 = __float2bfloat16(v0), h1 = __float2bfloat16(v1);
  __nv_bfloat162 hh; hh.x = h0; hh.y = h1;
  *(__nv_bfloat162*)&H[i] = hh;
  __nv_bfloat162 ll;
  ll.x = __float2bfloat16(v0 - __bfloat162float(h0));
  ll.y = __float2bfloat16(v1 - __bfloat162float(h1));
  *(__nv_bfloat162*)&L[i] = ll;
}

// Fast exp on the FMA pipe: exp(x)=2^(x*log2e), x<=0. rel err ~7e-7.
__device__ __forceinline__ float fexp_(float x){
  float t = fmaxf(x * 1.4426950408889634f, -126.f);
  float fi = floorf(t);
  float f = t - fi;
  float p = 1.5252733804e-5f;
  p = fmaf(p, f, 1.5403530394e-4f);
  p = fmaf(p, f, 1.3333558146e-3f);
  p = fmaf(p, f, 9.6181291076e-3f);
  p = fmaf(p, f, 5.5504108664e-2f);
  p = fmaf(p, f, 2.4022650696e-1f);
  p = fmaf(p, f, 6.9314718056e-1f);
  p = fmaf(p, f, 1.0f);
  return __int_as_float(((int)fi + 127) << 23) * p;
}

// QK epilogue scatter of an adjacent pos pair (pos even -> same patch, idx,idx+1).
__device__ __forceinline__ void qk_scat2(int bb, int tt, int ch, int pos,
    float v0, float v1,
    __nv_bfloat16* H0, __nv_bfloat16* Lo0, __nv_bfloat16* H1, __nv_bfloat16* Lo1)
{
  int y = pos >> 6, x = pos & 63;
  if (ch < 64) {
    int idx = (bb*L0 + tt*256 + (y>>2)*16 + (x>>2))*D0 + ch*16 + (y&3)*4 + (x&3);
    store2_(H0, Lo0, idx, v0, v1);
  } else {
    int idx = (bb*L1 + tt*64 + (y>>3)*8 + (x>>3))*D1 + (ch-64)*64 + (y&7)*8 + (x&7);
    store2_(H1, Lo1, idx, v0, v1);
  }
}

// PV epilogue scatter of an adjacent feature pair (f even -> dst,dst+1).
__device__ __forceinline__ void pv_scat2(int b, int l, int f, float v0, float v1, int scale)
{
  int dst;
  if (!scale) {
    int ch = f >> 4, pr = f & 15, tt = l >> 8, lrr = l & 255;
    dst = ((b*TT+tt)*CCH + ch)*SP + ((lrr>>4)*4 + (pr>>2))*64 + (lrr&15)*4 + (pr&3);
  } else {
    int ch = f >> 6, pr = f & 63, tt = l >> 6, lrr = l & 63;
    dst = ((b*TT+tt)*CCH + 64 + ch)*SP + ((lrr>>3)*8 + (pr>>3))*64 + (lrr&7)*8 + (pr&7);
  }
  store2_(g_attnh, g_attnl, dst, v0, v1);
}

#define MMA_BF16(c, a, b)                                               \
  asm volatile(                                                         \
    "mma.sync.aligned.m16n8k16.row.col.f32.bf16.bf16.f32 "              \
    "{%0,%1,%2,%3}, {%4,%5,%6,%7}, {%8,%9}, {%0,%1,%2,%3};"             \
    : "+f"((c)[0]), "+f"((c)[1]), "+f"((c)[2]), "+f"((c)[3])            \
    : "r"((a)[0]), "r"((a)[1]), "r"((a)[2]), "r"((a)[3]),               \
      "r"((b)[0]), "r"((b)[1]))

#define CP16(dst, src) \
  asm volatile("cp.async.ca.shared.global [%0], [%1], 16;" :: "r"(dst), "l"(src))
#define CPCOMMIT() asm volatile("cp.async.commit_group;" ::: "memory")
#define CPWAIT0()  asm volatile("cp.async.wait_group 0;" ::: "memory")
#define CPWAIT1()  asm volatile("cp.async.wait_group 1;" ::: "memory")

// ---------------- 0a: x transpose -> bf16 hi/lo [n][pos][in] ----------------
__global__ void k_xprep(const float* __restrict__ x)
{
  __shared__ float t[32][33];
  int n = blockIdx.z;
  int pos0 = blockIdx.x*32, in0 = blockIdx.y*32;
  int tx = threadIdx.x & 31, ty = threadIdx.x >> 5;
  const float* xp = x + (size_t)n*PLANE;
  #pragma unroll
  for (int i = 0; i < 4; i++)
    t[ty+8*i][tx] = xp[(size_t)(in0+ty+8*i)*SP + pos0+tx];
  __syncthreads();
  #pragma unroll
  for (int i = 0; i < 4; i++) {
    int p = ty + 8*i;
    size_t o = (size_t)n*PLANE + (size_t)(pos0+p)*CCH + in0 + tx;
    split_(t[tx][p], g_xTh, g_xTl, (int)o);
  }
}

// ---------------- 0b: weights -> bf16 hi/lo ----------------
__global__ void k_wprep(const float* __restrict__ wo, const float* __restrict__ wq,
                        const float* __restrict__ wk, const float* __restrict__ wv)
{
  int idx = blockIdx.x*256 + threadIdx.x;
  if (idx < CCH*1152) { split_(wo[idx], g_woh, g_wol, idx); return; }
  int r = idx - CCH*1152;
  if (r < CCH*CCH)        split_(wq[r], g_wqh, g_wql, r);
  else if (r < 2*CCH*CCH) split_(wk[r-CCH*CCH], g_wkh, g_wkl, r-CCH*CCH);
  else if (r < 3*CCH*CCH) split_(wv[r-2*CCH*CCH], g_wvh, g_wvl, r-2*CCH*CCH);
}

// ---------------- 2: depthwise 3x3 vle conv added into V ----------------
__global__ void k_vle(const float* __restrict__ x,
                      const float* __restrict__ wvle, const float* __restrict__ bvle)
{
  int idx = blockIdx.x*blockDim.x + threadIdx.x;
  if (idx >= BT*PLANE) return;
  int p  = idx & (SP-1);
  int ch = (idx >> 12) & 127;
  int y  = p >> 6, xx = p & 63;
  const float* xp = x + (size_t)(idx - p);
  const float* wp = wvle + ch*9;
  float s = bvle[ch];
  #pragma unroll
  for (int ky = 0; ky < 3; ky++) {
    int iy = y + ky - 1; if ((unsigned)iy >= 64u) continue;
    #pragma unroll
    for (int kx = 0; kx < 3; kx++) {
      int ix = xx + kx - 1; if ((unsigned)ix >= 64u) continue;
      s += wp[ky*3+kx] * xp[iy*64+ix];
    }
  }
  g_v[idx] += s;
}

// ---------------- 3: fused depth conv ----------------
__global__ void __launch_bounds__(256) k_depth(
    const float* __restrict__ dm,
    const float* __restrict__ wd1, const float* __restrict__ bd1,
    const float* __restrict__ wd2, const float* __restrict__ bd2)
{
  __shared__ float sdep[67][68];
  __shared__ float sd1[4][33][34];
  __shared__ float w1s[CCH*9];
  __shared__ float w2s[CCH*9];
  __shared__ float b1s[CCH];
  int n = blockIdx.y;
  int TY = blockIdx.x >> 2, TX = blockIdx.x & 3;
  int tid = threadIdx.x;
  for (int i = tid; i < CCH*9; i += 256) { w1s[i] = wd1[i]; w2s[i] = wd2[i]; }
  for (int i = tid; i < CCH;   i += 256) b1s[i] = bd1[i];
  const float* dmp = dm + (size_t)n*65536;
  int gy0 = TY*64 - 3, gx0 = TX*64 - 3;
  for (int i = tid; i < 67*67; i += 256) {
    int r = i/67, c = i - r*67;
    int gy = gy0 + r, gx = gx0 + c;
    float v = 0.f;
    if ((unsigned)gy < 256u && (unsigned)gx < 256u) v = dmp[gy*256+gx];
    sdep[r][c] = v;
  }
  int oy = tid >> 4, ox = tid & 15;
  int d1r0 = TY*32 - 1, d1c0 = TX*32 - 1;
  float acc = bd2[0];
  __syncthreads();
  for (int c0 = 0; c0 < CCH; c0 += 4) {
    for (int i = tid; i < 4*33*33; i += 256) {
      int cc = i / 1089;
      int rr = i - cc*1089;
      int dr = rr / 33, dc = rr - dr*33;
      const float* wc = &w1s[(c0+cc)*9];
      float s = b1s[c0+cc];
      #pragma unroll
      for (int ky = 0; ky < 3; ky++)
        #pragma unroll
        for (int kx = 0; kx < 3; kx++)
          s += wc[ky*3+kx] * sdep[2*dr+ky][2*dc+kx];
      int gr = d1r0 + dr, gc = d1c0 + dc;
      s = ((unsigned)gr < 128u && (unsigned)gc < 128u) ? fmaxf(s, 0.f) : 0.f;
      sd1[cc][dr][dc] = s;
    }
    __syncthreads();
    #pragma unroll
    for (int cc = 0; cc < 4; cc++) {
      const float* wc = &w2s[(c0+cc)*9];
      #pragma unroll
      for (int ky = 0; ky < 3; ky++)
        #pragma unroll
        for (int kx = 0; kx < 3; kx++)
          acc += wc[ky*3+kx] * sd1[cc][2*oy+ky][2*ox+kx];
    }
    __syncthreads();
  }
  g_depth[(size_t)n*4096 + (TY*16+oy)*64 + TX*16+ox] = fmaxf(acc, 0.f);
}

// ---------------- 5b: patchify V transposed -> bf16 hi/lo, [b][d][l] ----------------
__global__ void k_patch_vt(int scale)
{
  int idx = blockIdx.x*256 + threadIdx.x;
  int L = scale? L1:L0, D = scale? D1:D0, PH = scale? 8:4, OH = scale? 8:16;
  if (idx >= 2*L*D) return;
  int b = idx / (L*D);
  int r = idx - b*L*D;
  int d = r / L;
  int l = r - d*L;
  int pp = PH*PH;
  int ch = d / pp;
  int pr = d - ch*pp;
  int py = pr / PH, px = pr - py*PH;
  int oo = OH*OH;
  int tt = l / oo;
  int lr2 = l - tt*oo;
  int oh = lr2 / OH, ow = lr2 - oh*OH;
  int src = ((b*TT+tt)*CCH + scale*64 + ch)*SP + (oh*PH+py)*64 + ow*PH + px;
  float v = g_v[src];
  __nv_bfloat16* Vh = scale? g_Vt1h : g_Vt0h;
  __nv_bfloat16* Vl = scale? g_Vt1l : g_Vt0l;
  split_(v, Vh, Vl, idx);
}

// ---------------- 6: per-patch mask + depth stats ----------------
__global__ void k_stats(const float* __restrict__ m, int scale)
{
  int L = scale? L1:L0, PH = scale? 8:4, OH = scale? 8:16;
  int HW = PH*PH, MED = (HW-1)/2;
  int idx = blockIdx.x*blockDim.x + threadIdx.x;
  if (idx >= 2*L) return;
  int b = idx / L, l = idx - b*L;
  int oo = OH*OH;
  int tt = l / oo;
  int lr = l - tt*oo;
  int oh = lr / OH, ow = lr - oh*OH;
  int y0 = oh*PH, x0 = ow*PH;
  const float* mp = m + (size_t)(b*TT+tt)*4096;
  float s = 0.f;
  for (int py = 0; py < PH; py++)
    for (int px = 0; px < PH; px++)
      s += mp[(y0+py)*64 + x0+px];
  (scale? g_mask1 : g_mask0)[idx] = (s/(float)HW > 0.5f) ? 1.f : 0.f;

  const float* dp = g_depth + (size_t)(b*TT+tt)*4096;
  float buf[64];
  for (int i = 0; i < HW; i++) {
    int py = i / PH, px = i - py*PH;
    buf[i] = dp[(y0+py)*64 + x0+px];
  }
  float mn = buf[0], mx = buf[0];
  for (int i = 1; i < HW; i++) { mn = fminf(mn, buf[i]); mx = fmaxf(mx, buf[i]); }
  float med = buf[0];
  for (int i = 0; i < HW; i++) {
    int cnt = 0;
    for (int j = 0; j < HW; j++)
      cnt += (buf[j] < buf[i]) || (buf[j] == buf[i] && j < i);
    if (cnt == MED) med = buf[i];
  }
  float* sg = (scale? g_sig1 : g_sig0) + (size_t)b*3*L;
  sg[l]       = sigmoidf_(med);
  sg[L + l]   = sigmoidf_(mx);
  sg[2*L + l] = sigmoidf_(mn);
}

// ---------------- 7: fused hi/lo NT GEMM, 128x128x32, double-buffered cp.async ----------------
// emode: 0 = dense fp32 out, 1 = QK patched scatter, 2/3 = PV unpatch scatter (scale0/1)
__global__ void __launch_bounds__(256,2) k_gemm_nt(int which, const float* __restrict__ bias)
{
  extern __shared__ __align__(16) __nv_bfloat16 smp[];
  const __nv_bfloat16 *Ah, *Al, *Bh, *Bl;
  float *Cd = nullptr, *Cp = nullptr;
  __nv_bfloat16 *H0 = nullptr, *Lo0 = nullptr, *H1 = nullptr, *Lo1 = nullptr;
  int M, N, K, ns, ashare = 0, emode = 0; float scl = 1.f;
  if (which == 0)      { Ah=g_Q0h; Al=g_Q0l; Bh=g_K0h;  Bl=g_K0l;  Cd=g_S0;
                         M=L0; N=L0; K=D0; ns=1; scl=0.03125f; }
  else if (which == 1) { Ah=g_Q1h; Al=g_Q1l; Bh=g_K1h;  Bl=g_K1l;  Cp=g_S1p;
                         M=L1; N=L1; K=D1; ns=NS1; }
  else if (which == 2) { Ah=g_P0h; Al=g_P0l; Bh=g_Vt0h; Bl=g_Vt0l;
                         M=L0; N=D0; K=L0; ns=1; emode=2; }
  else if (which == 3) { Ah=g_P1h; Al=g_P1l; Bh=g_Vt1h; Bl=g_Vt1l;
                         M=L1; N=D1; K=L1; ns=1; emode=3; }
  else if (which == 4) { Ah=g_wqh; Al=g_wql; Bh=g_xTh;  Bl=g_xTl;
                         M=CCH; N=SP; K=CCH; ns=1; ashare=1; emode=1;
                         H0=g_Q0h; Lo0=g_Q0l; H1=g_Q1h; Lo1=g_Q1l; }
  else if (which == 5) { Ah=g_wkh; Al=g_wkl; Bh=g_xTh;  Bl=g_xTl;
                         M=CCH; N=SP; K=CCH; ns=1; ashare=1; emode=1;
                         H0=g_K0h; Lo0=g_K0l; H1=g_K1h; Lo1=g_K1l; }
  else                 { Ah=g_wvh; Al=g_wvl; Bh=g_xTh;  Bl=g_xTl;  Cd=g_v;
                         M=CCH; N=SP; K=CCH; ns=1; ashare=1; }

  int z = blockIdx.z;
  int b = z / ns, sp = z - b*ns;
  int Kc = K / ns;
  size_t aoff = (ashare ? 0 : (size_t)b*M*K) + (size_t)sp*Kc;
  size_t boff = (size_t)b*N*K + (size_t)sp*Kc;
  int row0 = blockIdx.y*128, col0 = blockIdx.x*128;
  int tid = threadIdx.x, lane = tid&31, wid = tid>>5;
  int wm = (wid&1)*64, wn = (wid>>1)*32;
  int lr = tid>>1, lc8 = (tid&1)*16;
  const __nv_bfloat16* Ahp = Ah + aoff + (size_t)(row0+lr)*K + lc8;
  const __nv_bfloat16* Alp = Al + aoff + (size_t)(row0+lr)*K + lc8;
  const __nv_bfloat16* Bhp = Bh + boff + (size_t)(col0+lr)*K + lc8;
  const __nv_bfloat16* Blp = Bl + boff + (size_t)(col0+lr)*K + lc8;
  unsigned sbase = (unsigned)__cvta_generic_to_shared(smp);
  unsigned rofs = (unsigned)((lr*PADC + lc8)*2);   // 80B row stride -> 16B aligned
  float c[4][4][4] = {};
  int nkb = Kc/32;

  // prefetch k-block 0 into stage 0
  CP16(sbase + rofs,            Ahp);  CP16(sbase + rofs + 16,            Ahp + 8);
  CP16(sbase + TILE_B + rofs,   Alp);  CP16(sbase + TILE_B + rofs + 16,   Alp + 8);
  CP16(sbase + 2*TILE_B + rofs, Bhp);  CP16(sbase + 2*TILE_B + rofs + 16, Bhp + 8);
  CP16(sbase + 3*TILE_B + rofs, Blp);  CP16(sbase + 3*TILE_B + rofs + 16, Blp + 8);
  CPCOMMIT();

  for (int kb = 0; kb < nkb; kb++) {
    int cur = kb & 1;
    if (kb+1 < nkb) {
      unsigned st = sbase + (unsigned)((cur^1)*STAGE_B);
      int o = (kb+1)*32;
      CP16(st + rofs,            Ahp + o);  CP16(st + rofs + 16,            Ahp + o + 8);
      CP16(st + TILE_B + rofs,   Alp + o);  CP16(st + TILE_B + rofs + 16,   Alp + o + 8);
      CP16(st + 2*TILE_B + rofs, Bhp + o);  CP16(st + 2*TILE_B + rofs + 16, Bhp + o + 8);
      CP16(st + 3*TILE_B + rofs, Blp + o);  CP16(st + 3*TILE_B + rofs + 16, Blp + o + 8);
      CPCOMMIT();
      CPWAIT1();
    } else {
      CPWAIT0();
    }
    __syncthreads();
    const __nv_bfloat16* Ahs = smp + cur*STAGE_E;
    const __nv_bfloat16* Als = Ahs + TILE_E;
    const __nv_bfloat16* Bhs = Ahs + 2*TILE_E;
    const __nv_bfloat16* Bls = Ahs + 3*TILE_E;
    #pragma unroll
    for (int ks = 0; ks < 2; ks++) {
      int kk = ks*16 + (lane&3)*2;
      unsigned af[4][4], bfh[4][2], bfl[4][2];
      #pragma unroll
      for (int mi = 0; mi < 4; mi++) {
        int r = wm + mi*16 + (lane>>2);
        af[mi][0] = *(const unsigned*)&Ahs[r*PADC + kk];
        af[mi][1] = *(const unsigned*)&Ahs[(r+8)*PADC + kk];
        af[mi][2] = *(const unsigned*)&Ahs[r*PADC + kk+8];
        af[mi][3] = *(const unsigned*)&Ahs[(r+8)*PADC + kk+8];
      }
      #pragma unroll
      for (int ni = 0; ni < 4; ni++) {
        int nn = wn + ni*8 + (lane>>2);
        bfh[ni][0] = *(const unsigned*)&Bhs[nn*PADC + kk];
        bfh[ni][1] = *(const unsigned*)&Bhs[nn*PADC + kk+8];
        bfl[ni][0] = *(const unsigned*)&Bls[nn*PADC + kk];
        bfl[ni][1] = *(const unsigned*)&Bls[nn*PADC + kk+8];
      }
      #pragma unroll
      for (int mi = 0; mi < 4; mi++)
        #pragma unroll
        for (int ni = 0; ni < 4; ni++) {
          MMA_BF16(c[mi][ni], af[mi], bfh[ni]);
          MMA_BF16(c[mi][ni], af[mi], bfl[ni]);
        }
      #pragma unroll
      for (int mi = 0; mi < 4; mi++) {
        int r = wm + mi*16 + (lane>>2);
        af[mi][0] = *(const unsigned*)&Als[r*PADC + kk];
        af[mi][1] = *(const unsigned*)&Als[(r+8)*PADC + kk];
        af[mi][2] = *(const unsigned*)&Als[r*PADC + kk+8];
        af[mi][3] = *(const unsigned*)&Als[(r+8)*PADC + kk+8];
      }
      #pragma unroll
      for (int mi = 0; mi < 4; mi++)
        #pragma unroll
        for (int ni = 0; ni < 4; ni++)
          MMA_BF16(c[mi][ni], af[mi], bfh[ni]);
    }
    __syncthreads();
  }

  if (emode == 0) {
    float* Co;
    if (ns > 1) Co = Cp + ((size_t)sp*BATCH + b)*M*N;
    else        Co = Cd + (size_t)b*M*N;
    #pragma unroll
    for (int mi = 0; mi < 4; mi++) {
      int r = row0 + wm + mi*16 + (lane>>2);
      float b0 = bias ? bias[r]   : 0.f;
      float b1 = bias ? bias[r+8] : 0.f;
      #pragma unroll
      for (int ni = 0; ni < 4; ni++) {
        int cc = col0 + wn + ni*8 + (lane&3)*2;
        float2 v0 = make_float2(c[mi][ni][0]*scl + b0, c[mi][ni][1]*scl + b0);
        float2 v1 = make_float2(c[mi][ni][2]*scl + b1, c[mi][ni][3]*scl + b1);
        *(float2*)&Co[(size_t)r*N + cc]     = v0;
        *(float2*)&Co[(size_t)(r+8)*N + cc] = v1;
      }
    }
  } else if (emode == 1) {
    int bb = z >> 3, tt = z & 7;
    #pragma unroll
    for (int mi = 0; mi < 4; mi++) {
      int r = wm + mi*16 + (lane>>2);
      float b0 = bias[r], b1 = bias[r+8];
      #pragma unroll
      for (int ni = 0; ni < 4; ni++) {
        int cc = col0 + wn + ni*8 + (lane&3)*2;
        qk_scat2(bb, tt, r,   cc, c[mi][ni][0] + b0, c[mi][ni][1] + b0, H0, Lo0, H1, Lo1);
        qk_scat2(bb, tt, r+8, cc, c[mi][ni][2] + b1, c[mi][ni][3] + b1, H0, Lo0, H1, Lo1);
      }
    }
  } else {
    int sc1 = (emode == 3);
    #pragma unroll
    for (int mi = 0; mi < 4; mi++) {
      int r = row0 + wm + mi*16 + (lane>>2);
      #pragma unroll
      for (int ni = 0; ni < 4; ni++) {
        int cc = col0 + wn + ni*8 + (lane&3)*2;
        pv_scat2(b, r,   cc, c[mi][ni][0], c[mi][ni][1], sc1);
        pv_scat2(b, r+8, cc, c[mi][ni][2], c[mi][ni][3], sc1);
      }
    }
  }
}

// ---------------- 9: fused 3-head masked softmax (fast exp; scale1 sums split-K partials) ----------------
__device__ __forceinline__ float warp_max_(float v){
  #pragma unroll
  for (int o = 16; o; o >>= 1) v = fmaxf(v, __shfl_xor_sync(0xffffffffu, v, o));
  return v;
}
__device__ __forceinline__ float warp_sum_(float v){
  #pragma unroll
  for (int o = 16; o; o >>= 1) v += __shfl_xor_sync(0xffffffffu, v, o);
  return v;
}

__global__ void k_softmax(int scale)
{
  extern __shared__ float sv[];      // 3*L
  __shared__ float rbuf[3][8];
  int L = scale? L1:L0;
  const float* mk = (scale? g_mask1 : g_mask0) + (size_t)blockIdx.y*L;
  const float* sg = (scale? g_sig1  : g_sig0)  + (size_t)blockIdx.y*3*L;
  size_t rowoff = ((size_t)blockIdx.y*L + blockIdx.x)*L;
  const float* row0p = g_S0 + rowoff;
  const float* p1 = g_S1p + (size_t)blockIdx.y*L1*L1 + (size_t)blockIdx.x*L1;
  const size_t PS = (size_t)BATCH*L1*L1;
  __nv_bfloat16* Ph = scale? g_P1h : g_P0h;
  __nv_bfloat16* Pl = scale? g_P1l : g_P0l;
  int tid = threadIdx.x, lane = tid&31, wid = tid>>5;

  float m0 = -3e38f, m1 = -3e38f, m2 = -3e38f;
  for (int k = tid; k < L; k += 256) {
    float s;
    if (scale) s = (p1[k] + p1[k+PS] + p1[k+2*PS] + p1[k+3*PS]) * 0.015625f;
    else       s = row0p[k];
    float v0, v1, v2;
    if (mk[k] > 0.5f) { v0 = v1 = v2 = -1e9f; }
    else { v0 = s*sg[k]; v1 = s*sg[L+k]; v2 = s*sg[2*L+k]; }
    sv[k] = v0; sv[L+k] = v1; sv[2*L+k] = v2;
    m0 = fmaxf(m0, v0); m1 = fmaxf(m1, v1); m2 = fmaxf(m2, v2);
  }
  m0 = warp_max_(m0); m1 = warp_max_(m1); m2 = warp_max_(m2);
  if (lane == 0) { rbuf[0][wid]=m0; rbuf[1][wid]=m1; rbuf[2][wid]=m2; }
  __syncthreads();
  m0 = rbuf[0][0]; m1 = rbuf[1][0]; m2 = rbuf[2][0];
  #pragma unroll
  for (int w = 1; w < 8; w++) {
    m0 = fmaxf(m0, rbuf[0][w]); m1 = fmaxf(m1, rbuf[1][w]); m2 = fmaxf(m2, rbuf[2][w]);
  }
  __syncthreads();

  float z0 = 0.f, z1 = 0.f, z2 = 0.f;
  for (int k = tid; k < L; k += 256) {
    float e0 = fexp_(sv[k]     - m0);
    float e1 = fexp_(sv[L+k]   - m1);
    float e2 = fexp_(sv[2*L+k] - m2);
    sv[k] = e0; sv[L+k] = e1; sv[2*L+k] = e2;
    z0 += e0; z1 += e1; z2 += e2;
  }
  z0 = warp_sum_(z0); z1 = warp_sum_(z1); z2 = warp_sum_(z2);
  if (lane == 0) { rbuf[0][wid]=z0; rbuf[1][wid]=z1; rbuf[2][wid]=z2; }
  __syncthreads();
  z0 = 0.f; z1 = 0.f; z2 = 0.f;
  #pragma unroll
  for (int w = 0; w < 8; w++) { z0 += rbuf[0][w]; z1 += rbuf[1][w]; z2 += rbuf[2][w]; }
  float i0 = 1.f/(3.f*z0), i1 = 1.f/(3.f*z1), i2 = 1.f/(3.f*z2);
  for (int k = tid; k < L; k += 256) {
    float p = sv[k]*i0 + sv[L+k]*i1 + sv[2*L+k]*i2;
    split_(p, Ph, Pl, (int)(rowoff + k));
  }
}

// ---------------- 12: wo 3x3 conv, single-pass fused hi/lo implicit GEMM ----------------
__global__ void __launch_bounds__(256) k_conv_mma(
    const float* __restrict__ bo, float* __restrict__ out)
{
  __shared__ __align__(16) __nv_bfloat16 Ahs[128][40];
  __shared__ __align__(16) __nv_bfloat16 Als[128][40];
  __shared__ __align__(16) __nv_bfloat16 Bhs[128][40];
  __shared__ __align__(16) __nv_bfloat16 Bls[128][40];
  int n = blockIdx.z;
  int col0 = blockIdx.x*128;
  int tid = threadIdx.x, lane = tid&31, wid = tid>>5;
  int wm = (wid&1)*64, wn = (wid>>1)*32;
  int lr = tid>>1, lc = (tid&1)*16;
  int nloc = tid & 127, khalf = tid >> 7;
  int pos = col0 + nloc;
  int py = pos >> 6, px = pos & 63;
  const __nv_bfloat16* Bph = g_attnh + (size_t)n*PLANE;
  const __nv_bfloat16* Bpl = g_attnl + (size_t)n*PLANE;
  float c[4][4][4] = {};
  #pragma unroll 1
  for (int kb = 0; kb < 36; kb++) {
    __syncthreads();
    *(float4*)&Ahs[lr][lc]   = *(const float4*)(g_woh + (size_t)lr*1152 + kb*32 + lc);
    *(float4*)&Ahs[lr][lc+8] = *(const float4*)(g_woh + (size_t)lr*1152 + kb*32 + lc + 8);
    *(float4*)&Als[lr][lc]   = *(const float4*)(g_wol + (size_t)lr*1152 + kb*32 + lc);
    *(float4*)&Als[lr][lc+8] = *(const float4*)(g_wol + (size_t)lr*1152 + kb*32 + lc + 8);
    #pragma unroll
    for (int u = 0; u < 16; u++) {
      int k = kb*32 + khalf*16 + u;
      int ic = k/9;
      int rr = k - ic*9;
      int ky = rr/3 - 1, kx = rr - (rr/3)*3 - 1;
      int iy = py + ky, ix = px + kx;
      __nv_bfloat16 vh = __float2bfloat16(0.f), vl = vh;
      if ((unsigned)iy < 64u && (unsigned)ix < 64u) {
        size_t o = (size_t)ic*SP + iy*64 + ix;
        vh = Bph[o]; vl = Bpl[o];
      }
      Bhs[nloc][khalf*16 + u] = vh;
      Bls[nloc][khalf*16 + u] = vl;
    }
    __syncthreads();
    #pragma unroll
    for (int ks = 0; ks < 2; ks++) {
      int kk = ks*16 + (lane&3)*2;
      unsigned af[4][4], bfh[4][2], bfl[4][2];
      #pragma unroll
      for (int mi = 0; mi < 4; mi++) {
        int r = wm + mi*16 + (lane>>2);
        af[mi][0] = *(const unsigned*)&Ahs[r][kk];
        af[mi][1] = *(const unsigned*)&Ahs[r+8][kk];
        af[mi][2] = *(const unsigned*)&Ahs[r][kk+8];
        af[mi][3] = *(const unsigned*)&Ahs[r+8][kk+8];
      }
      #pragma unroll
      for (int ni = 0; ni < 4; ni++) {
        int nn = wn + ni*8 + (lane>>2);
        bfh[ni][0] = *(const unsigned*)&Bhs[nn][kk];
        bfh[ni][1] = *(const unsigned*)&Bhs[nn][kk+8];
        bfl[ni][0] = *(const unsigned*)&Bls[nn][kk];
        bfl[ni][1] = *(const unsigned*)&Bls[nn][kk+8];
      }
      #pragma unroll
      for (int mi = 0; mi < 4; mi++)
        #pragma unroll
        for (int ni = 0; ni < 4; ni++) {
          MMA_BF16(c[mi][ni], af[mi], bfh[ni]);
          MMA_BF16(c[mi][ni], af[mi], bfl[ni]);
        }
      #pragma unroll
      for (int mi = 0; mi < 4; mi++) {
        int r = wm + mi*16 + (lane>>2);
        af[mi][0] = *(const unsigned*)&Als[r][kk];
        af[mi][1] = *(const unsigned*)&Als[r+8][kk];
        af[mi][2] = *(const unsigned*)&Als[r][kk+8];
        af[mi][3] = *(const unsigned*)&Als[r+8][kk+8];
      }
      #pragma unroll
      for (int mi = 0; mi < 4; mi++)
        #pragma unroll
        for (int ni = 0; ni < 4; ni++)
          MMA_BF16(c[mi][ni], af[mi], bfh[ni]);
    }
  }
  #pragma unroll
  for (int mi = 0; mi < 4; mi++) {
    int r = wm + mi*16 + (lane>>2);
    float b0 = bo[r], b1 = bo[r+8];
    #pragma unroll
    for (int ni = 0; ni < 4; ni++) {
      int cc = col0 + wn + ni*8 + (lane&3)*2;
      float v0 = c[mi][ni][0] + b0, v1 = c[mi][ni][1] + b0;
      float v2 = c[mi][ni][2] + b1, v3 = c[mi][ni][3] + b1;
      v0 = (v0 >= 0.f) ? v0 : 0.2f*v0;
      v1 = (v1 >= 0.f) ? v1 : 0.2f*v1;
      v2 = (v2 >= 0.f) ? v2 : 0.2f*v2;
      v3 = (v3 >= 0.f) ? v3 : 0.2f*v3;
      *(float2*)&out[(size_t)n*PLANE + (size_t)r*SP + cc]     = make_float2(v0, v1);
      *(float2*)&out[(size_t)n*PLANE + (size_t)(r+8)*SP + cc] = make_float2(v2, v3);
    }
  }
}

// ---------------- host ----------------
extern "C" void kernel_launch(void* const* d_in, const int* in_sizes, int n_in,
                              void* d_out, int out_size)
{
  const float* x     = (const float*)d_in[0];
  const float* m     = (const float*)d_in[1];
  const float* dmap  = (const float*)d_in[2];
  const float* wq    = (const float*)d_in[3];
  const float* bq    = (const float*)d_in[4];
  const float* wk    = (const float*)d_in[5];
  const float* bk    = (const float*)d_in[6];
  const float* wv    = (const float*)d_in[7];
  const float* bv    = (const float*)d_in[8];
  const float* wvle  = (const float*)d_in[9];
  const float* bvle  = (const float*)d_in[10];
  const float* wd1   = (const float*)d_in[11];
  const float* bd1   = (const float*)d_in[12];
  const float* wd2   = (const float*)d_in[13];
  const float* bd2   = (const float*)d_in[14];
  const float* wo    = (const float*)d_in[15];
  const float* bo    = (const float*)d_in[16];
  float* out = (float*)d_out;

  cudaFuncSetAttribute(k_gemm_nt, cudaFuncAttributeMaxDynamicSharedMemorySize, GEMM_SMEM);

  k_xprep<<<dim3(128,4,16), 256>>>(x);
  k_wprep<<<(CCH*1152 + 3*CCH*CCH + 255)/256, 256>>>(wo, wq, wk, wv);

  k_gemm_nt<<<dim3(SP/128, 1, BT), 256, GEMM_SMEM>>>(4, bq);
  k_gemm_nt<<<dim3(SP/128, 1, BT), 256, GEMM_SMEM>>>(5, bk);
  k_gemm_nt<<<dim3(SP/128, 1, BT), 256, GEMM_SMEM>>>(6, bv);

  k_vle<<<(BT*PLANE)/256, 256>>>(x, wvle, bvle);
  k_depth<<<dim3(16,16), 256>>>(dmap, wd1, bd1, wd2, bd2);

  k_patch_vt<<<(2*L0*D0)/256, 256>>>(0);
  k_patch_vt<<<(2*L1*D1)/256, 256>>>(1);
  k_stats<<<(2*L0+255)/256, 256>>>(m, 0);
  k_stats<<<(2*L1+255)/256, 256>>>(m, 1);

  k_gemm_nt<<<dim3(L0/128, L0/128, BATCH), 256, GEMM_SMEM>>>(0, nullptr);
  k_gemm_nt<<<dim3(L1/128, L1/128, BATCH*NS1), 256, GEMM_SMEM>>>(1, nullptr);

  k_softmax<<<dim3(L0, BATCH), 256, 3*L0*sizeof(float)>>>(0);
  k_softmax<<<dim3(L1, BATCH), 256, 3*L1*sizeof(float)>>>(1);

  k_gemm_nt<<<dim3(D0/128, L0/128, BATCH), 256, GEMM_SMEM>>>(2, nullptr);
  k_gemm_nt<<<dim3(D1/128, L1/128, BATCH), 256, GEMM_SMEM>>>(3, nullptr);

  k_conv_mma<<<dim3(32,1,16), 256>>>(bo, out);

  cudaMemcpyAsync(out + BT*PLANE, dmap, (size_t)BT*65536*sizeof(float),
                  cudaMemcpyDeviceToDevice);
}

// round 17
// speedup vs baseline: 1.5835x; 1.0257x over previous
#include <cuda_runtime.h>
#include <cuda_bf16.h>

#define BT 16
#define BATCH 2
#define TT 8
#define CCH 128
#define SP 4096            // 64*64
#define PLANE (CCH*SP)     // 524288

#define L0 2048
#define D0 1024
#define L1 512
#define D1 4096
#define NS1 4              // split-K for scale1 scores

#define PADC 40
#define TILE_E (128*PADC)          // 5120 elements per matrix tile
#define TILE_B (TILE_E*2)          // 10240 bytes
#define STAGE_E (4*TILE_E)         // 20480 elements per stage
#define STAGE_B (4*TILE_B)         // 40960 bytes per stage
#define GEMM_SMEM (2*STAGE_B)      // 81920 bytes dynamic

// ---------------- scratch (static device memory; no allocation) ----------------
static __device__ float g_v[BT*PLANE];
static __device__ float g_depth[BT*64*64];
static __device__ float g_S0[BATCH*L0*L0];
static __device__ float g_S1p[NS1*BATCH*L1*L1];
static __device__ float g_mask0[BATCH*L0];
static __device__ float g_mask1[BATCH*L1];
static __device__ float g_sig0[BATCH*3*L0];
static __device__ float g_sig1[BATCH*3*L1];

// bf16 hi/lo operand buffers for tensor-core GEMMs
static __device__ __nv_bfloat16 g_Q0h[BATCH*L0*D0], g_Q0l[BATCH*L0*D0];
static __device__ __nv_bfloat16 g_K0h[BATCH*L0*D0], g_K0l[BATCH*L0*D0];
static __device__ __nv_bfloat16 g_Vt0h[BATCH*D0*L0], g_Vt0l[BATCH*D0*L0];
static __device__ __nv_bfloat16 g_Q1h[BATCH*L1*D1], g_Q1l[BATCH*L1*D1];
static __device__ __nv_bfloat16 g_K1h[BATCH*L1*D1], g_K1l[BATCH*L1*D1];
static __device__ __nv_bfloat16 g_Vt1h[BATCH*D1*L1], g_Vt1l[BATCH*D1*L1];
static __device__ __nv_bfloat16 g_P0h[BATCH*L0*L0], g_P0l[BATCH*L0*L0];
static __device__ __nv_bfloat16 g_P1h[BATCH*L1*L1], g_P1l[BATCH*L1*L1];
// attn output (pre-wo-conv) in bf16 hi/lo planes
static __device__ __nv_bfloat16 g_attnh[BT*PLANE], g_attnl[BT*PLANE];
// wo + qkv weights in bf16 hi/lo
static __device__ __nv_bfloat16 g_woh[CCH*1152], g_wol[CCH*1152];
static __device__ __nv_bfloat16 g_wqh[CCH*CCH], g_wql[CCH*CCH];
static __device__ __nv_bfloat16 g_wkh[CCH*CCH], g_wkl[CCH*CCH];
static __device__ __nv_bfloat16 g_wvh[CCH*CCH], g_wvl[CCH*CCH];
// x transposed per image: [n][pos][in] bf16 hi/lo
static __device__ __nv_bfloat16 g_xTh[BT*PLANE], g_xTl[BT*PLANE];

__device__ __forceinline__ float sigmoidf_(float x){ return 1.f/(1.f+__expf(-x)); }
__device__ __forceinline__ void split_(float v, __nv_bfloat16* h, __nv_bfloat16* l, int i){
  __nv_bfloat16 hh = __float2bfloat16(v);
  h[i] = hh; l[i] = __float2bfloat16(v - __bfloat162float(hh));
}
// Packed hi/lo store of an adjacent pair (i must be even; dest 4B aligned).
__device__ __forceinline__ void store2_(__nv_bfloat16* H, __nv_bfloat16* L, int i,
                                        float v0, float v1){
  __nv_bfloat16 h0 = __float2bfloat16(v0), h1 = __float2bfloat16(v1);
  __nv_bfloat162 hh; hh.x = h0; hh.y = h1;
  *(__nv_bfloat162*)&H[i] = hh;
  __nv_bfloat162 ll;
  ll.x = __float2bfloat16(v0 - __bfloat162float(h0));
  ll.y = __float2bfloat16(v1 - __bfloat162float(h1));
  *(__nv_bfloat162*)&L[i] = ll;
}

// Fast exp on the FMA pipe: exp(x)=2^(x*log2e), x<=0. rel err ~7e-7.
__device__ __forceinline__ float fexp_(float x){
  float t = fmaxf(x * 1.4426950408889634f, -126.f);
  float fi = floorf(t);
  float f = t - fi;
  float p = 1.5252733804e-5f;
  p = fmaf(p, f, 1.5403530394e-4f);
  p = fmaf(p, f, 1.3333558146e-3f);
  p = fmaf(p, f, 9.6181291076e-3f);
  p = fmaf(p, f, 5.5504108664e-2f);
  p = fmaf(p, f, 2.4022650696e-1f);
  p = fmaf(p, f, 6.9314718056e-1f);
  p = fmaf(p, f, 1.0f);
  return __int_as_float(((int)fi + 127) << 23) * p;
}

// QK epilogue scatter of an adjacent pos pair (pos even -> same patch, idx,idx+1).
__device__ __forceinline__ void qk_scat2(int bb, int tt, int ch, int pos,
    float v0, float v1,
    __nv_bfloat16* H0, __nv_bfloat16* Lo0, __nv_bfloat16* H1, __nv_bfloat16* Lo1)
{
  int y = pos >> 6, x = pos & 63;
  if (ch < 64) {
    int idx = (bb*L0 + tt*256 + (y>>2)*16 + (x>>2))*D0 + ch*16 + (y&3)*4 + (x&3);
    store2_(H0, Lo0, idx, v0, v1);
  } else {
    int idx = (bb*L1 + tt*64 + (y>>3)*8 + (x>>3))*D1 + (ch-64)*64 + (y&7)*8 + (x&7);
    store2_(H1, Lo1, idx, v0, v1);
  }
}

// PV epilogue scatter of an adjacent feature pair (f even -> dst,dst+1).
__device__ __forceinline__ void pv_scat2(int b, int l, int f, float v0, float v1, int scale)
{
  int dst;
  if (!scale) {
    int ch = f >> 4, pr = f & 15, tt = l >> 8, lrr = l & 255;
    dst = ((b*TT+tt)*CCH + ch)*SP + ((lrr>>4)*4 + (pr>>2))*64 + (lrr&15)*4 + (pr&3);
  } else {
    int ch = f >> 6, pr = f & 63, tt = l >> 6, lrr = l & 63;
    dst = ((b*TT+tt)*CCH + 64 + ch)*SP + ((lrr>>3)*8 + (pr>>3))*64 + (lrr&7)*8 + (pr&7);
  }
  store2_(g_attnh, g_attnl, dst, v0, v1);
}

#define MMA_BF16(c, a, b)                                               \
  asm volatile(                                                         \
    "mma.sync.aligned.m16n8k16.row.col.f32.bf16.bf16.f32 "              \
    "{%0,%1,%2,%3}, {%4,%5,%6,%7}, {%8,%9}, {%0,%1,%2,%3};"             \
    : "+f"((c)[0]), "+f"((c)[1]), "+f"((c)[2]), "+f"((c)[3])            \
    : "r"((a)[0]), "r"((a)[1]), "r"((a)[2]), "r"((a)[3]),               \
      "r"((b)[0]), "r"((b)[1]))

#define CP16(dst, src) \
  asm volatile("cp.async.ca.shared.global [%0], [%1], 16;" :: "r"(dst), "l"(src))
#define CPCOMMIT() asm volatile("cp.async.commit_group;" ::: "memory")
#define CPWAIT0()  asm volatile("cp.async.wait_group 0;" ::: "memory")
#define CPWAIT1()  asm volatile("cp.async.wait_group 1;" ::: "memory")

// ---------------- 0a: x transpose -> bf16 hi/lo [n][pos][in] ----------------
__global__ void k_xprep(const float* __restrict__ x)
{
  __shared__ float t[32][33];
  int n = blockIdx.z;
  int pos0 = blockIdx.x*32, in0 = blockIdx.y*32;
  int tx = threadIdx.x & 31, ty = threadIdx.x >> 5;
  const float* xp = x + (size_t)n*PLANE;
  #pragma unroll
  for (int i = 0; i < 4; i++)
    t[ty+8*i][tx] = xp[(size_t)(in0+ty+8*i)*SP + pos0+tx];
  __syncthreads();
  #pragma unroll
  for (int i = 0; i < 4; i++) {
    int p = ty + 8*i;
    size_t o = (size_t)n*PLANE + (size_t)(pos0+p)*CCH + in0 + tx;
    split_(t[tx][p], g_xTh, g_xTl, (int)o);
  }
}

// ---------------- 0b: weights -> bf16 hi/lo ----------------
__global__ void k_wprep(const float* __restrict__ wo, const float* __restrict__ wq,
                        const float* __restrict__ wk, const float* __restrict__ wv)
{
  int idx = blockIdx.x*256 + threadIdx.x;
  if (idx < CCH*1152) { split_(wo[idx], g_woh, g_wol, idx); return; }
  int r = idx - CCH*1152;
  if (r < CCH*CCH)        split_(wq[r], g_wqh, g_wql, r);
  else if (r < 2*CCH*CCH) split_(wk[r-CCH*CCH], g_wkh, g_wkl, r-CCH*CCH);
  else if (r < 3*CCH*CCH) split_(wv[r-2*CCH*CCH], g_wvh, g_wvl, r-2*CCH*CCH);
}

// ---------------- 2: depthwise 3x3 vle conv added into V ----------------
__global__ void k_vle(const float* __restrict__ x,
                      const float* __restrict__ wvle, const float* __restrict__ bvle)
{
  int idx = blockIdx.x*blockDim.x + threadIdx.x;
  if (idx >= BT*PLANE) return;
  int p  = idx & (SP-1);
  int ch = (idx >> 12) & 127;
  int y  = p >> 6, xx = p & 63;
  const float* xp = x + (size_t)(idx - p);
  const float* wp = wvle + ch*9;
  float s = bvle[ch];
  #pragma unroll
  for (int ky = 0; ky < 3; ky++) {
    int iy = y + ky - 1; if ((unsigned)iy >= 64u) continue;
    #pragma unroll
    for (int kx = 0; kx < 3; kx++) {
      int ix = xx + kx - 1; if ((unsigned)ix >= 64u) continue;
      s += wp[ky*3+kx] * xp[iy*64+ix];
    }
  }
  g_v[idx] += s;
}

// ---------------- 3: fused depth conv ----------------
__global__ void __launch_bounds__(256) k_depth(
    const float* __restrict__ dm,
    const float* __restrict__ wd1, const float* __restrict__ bd1,
    const float* __restrict__ wd2, const float* __restrict__ bd2)
{
  __shared__ float sdep[67][68];
  __shared__ float sd1[4][33][34];
  __shared__ float w1s[CCH*9];
  __shared__ float w2s[CCH*9];
  __shared__ float b1s[CCH];
  int n = blockIdx.y;
  int TY = blockIdx.x >> 2, TX = blockIdx.x & 3;
  int tid = threadIdx.x;
  for (int i = tid; i < CCH*9; i += 256) { w1s[i] = wd1[i]; w2s[i] = wd2[i]; }
  for (int i = tid; i < CCH;   i += 256) b1s[i] = bd1[i];
  const float* dmp = dm + (size_t)n*65536;
  int gy0 = TY*64 - 3, gx0 = TX*64 - 3;
  for (int i = tid; i < 67*67; i += 256) {
    int r = i/67, c = i - r*67;
    int gy = gy0 + r, gx = gx0 + c;
    float v = 0.f;
    if ((unsigned)gy < 256u && (unsigned)gx < 256u) v = dmp[gy*256+gx];
    sdep[r][c] = v;
  }
  int oy = tid >> 4, ox = tid & 15;
  int d1r0 = TY*32 - 1, d1c0 = TX*32 - 1;
  float acc = bd2[0];
  __syncthreads();
  for (int c0 = 0; c0 < CCH; c0 += 4) {
    for (int i = tid; i < 4*33*33; i += 256) {
      int cc = i / 1089;
      int rr = i - cc*1089;
      int dr = rr / 33, dc = rr - dr*33;
      const float* wc = &w1s[(c0+cc)*9];
      float s = b1s[c0+cc];
      #pragma unroll
      for (int ky = 0; ky < 3; ky++)
        #pragma unroll
        for (int kx = 0; kx < 3; kx++)
          s += wc[ky*3+kx] * sdep[2*dr+ky][2*dc+kx];
      int gr = d1r0 + dr, gc = d1c0 + dc;
      s = ((unsigned)gr < 128u && (unsigned)gc < 128u) ? fmaxf(s, 0.f) : 0.f;
      sd1[cc][dr][dc] = s;
    }
    __syncthreads();
    #pragma unroll
    for (int cc = 0; cc < 4; cc++) {
      const float* wc = &w2s[(c0+cc)*9];
      #pragma unroll
      for (int ky = 0; ky < 3; ky++)
        #pragma unroll
        for (int kx = 0; kx < 3; kx++)
          acc += wc[ky*3+kx]*sd1[cc][2*oy+ky][2*ox+kx];
    }
    __syncthreads();
  }
  g_depth[(size_t)n*4096 + (TY*16+oy)*64 + TX*16+ox] = fmaxf(acc, 0.f);
}

// ---------------- 5b: patchify V transposed -> bf16 hi/lo, [b][d][l] ----------------
__global__ void k_patch_vt(int scale)
{
  int idx = blockIdx.x*256 + threadIdx.x;
  int L = scale? L1:L0, D = scale? D1:D0, PH = scale? 8:4, OH = scale? 8:16;
  if (idx >= 2*L*D) return;
  int b = idx / (L*D);
  int r = idx - b*L*D;
  int d = r / L;
  int l = r - d*L;
  int pp = PH*PH;
  int ch = d / pp;
  int pr = d - ch*pp;
  int py = pr / PH, px = pr - py*PH;
  int oo = OH*OH;
  int tt = l / oo;
  int lr2 = l - tt*oo;
  int oh = lr2 / OH, ow = lr2 - oh*OH;
  int src = ((b*TT+tt)*CCH + scale*64 + ch)*SP + (oh*PH+py)*64 + ow*PH + px;
  float v = g_v[src];
  __nv_bfloat16* Vh = scale? g_Vt1h : g_Vt0h;
  __nv_bfloat16* Vl = scale? g_Vt1l : g_Vt0l;
  split_(v, Vh, Vl, idx);
}

// ---------------- 6: per-patch mask + depth stats ----------------
__global__ void k_stats(const float* __restrict__ m, int scale)
{
  int L = scale? L1:L0, PH = scale? 8:4, OH = scale? 8:16;
  int HW = PH*PH, MED = (HW-1)/2;
  int idx = blockIdx.x*blockDim.x + threadIdx.x;
  if (idx >= 2*L) return;
  int b = idx / L, l = idx - b*L;
  int oo = OH*OH;
  int tt = l / oo;
  int lr = l - tt*oo;
  int oh = lr / OH, ow = lr - oh*OH;
  int y0 = oh*PH, x0 = ow*PH;
  const float* mp = m + (size_t)(b*TT+tt)*4096;
  float s = 0.f;
  for (int py = 0; py < PH; py++)
    for (int px = 0; px < PH; px++)
      s += mp[(y0+py)*64 + x0+px];
  (scale? g_mask1 : g_mask0)[idx] = (s/(float)HW > 0.5f) ? 1.f : 0.f;

  const float* dp = g_depth + (size_t)(b*TT+tt)*4096;
  float buf[64];
  for (int i = 0; i < HW; i++) {
    int py = i / PH, px = i - py*PH;
    buf[i] = dp[(y0+py)*64 + x0+px];
  }
  float mn = buf[0], mx = buf[0];
  for (int i = 1; i < HW; i++) { mn = fminf(mn, buf[i]); mx = fmaxf(mx, buf[i]); }
  float med = buf[0];
  for (int i = 0; i < HW; i++) {
    int cnt = 0;
    for (int j = 0; j < HW; j++)
      cnt += (buf[j] < buf[i]) || (buf[j] == buf[i] && j < i);
    if (cnt == MED) med = buf[i];
  }
  float* sg = (scale? g_sig1 : g_sig0) + (size_t)b*3*L;
  sg[l]       = sigmoidf_(med);
  sg[L + l]   = sigmoidf_(mx);
  sg[2*L + l] = sigmoidf_(mn);
}

// ---------------- 7: fused hi/lo NT GEMM, 128x128x32, double-buffered cp.async ----------------
// emode: 0 = dense fp32 out, 1 = QK patched scatter, 2/3 = PV unpatch scatter (scale0/1)
__global__ void __launch_bounds__(256,2) k_gemm_nt(int which, const float* __restrict__ bias)
{
  extern __shared__ __align__(16) __nv_bfloat16 smp[];
  const __nv_bfloat16 *Ah, *Al, *Bh, *Bl;
  float *Cd = nullptr, *Cp = nullptr;
  __nv_bfloat16 *H0 = nullptr, *Lo0 = nullptr, *H1 = nullptr, *Lo1 = nullptr;
  int M, N, K, ns, ashare = 0, emode = 0; float scl = 1.f;
  if (which == 0)      { Ah=g_Q0h; Al=g_Q0l; Bh=g_K0h;  Bl=g_K0l;  Cd=g_S0;
                         M=L0; N=L0; K=D0; ns=1; scl=0.03125f; }
  else if (which == 1) { Ah=g_Q1h; Al=g_Q1l; Bh=g_K1h;  Bl=g_K1l;  Cp=g_S1p;
                         M=L1; N=L1; K=D1; ns=NS1; }
  else if (which == 2) { Ah=g_P0h; Al=g_P0l; Bh=g_Vt0h; Bl=g_Vt0l;
                         M=L0; N=D0; K=L0; ns=1; emode=2; }
  else if (which == 3) { Ah=g_P1h; Al=g_P1l; Bh=g_Vt1h; Bl=g_Vt1l;
                         M=L1; N=D1; K=L1; ns=1; emode=3; }
  else if (which == 4) { Ah=g_wqh; Al=g_wql; Bh=g_xTh;  Bl=g_xTl;
                         M=CCH; N=SP; K=CCH; ns=1; ashare=1; emode=1;
                         H0=g_Q0h; Lo0=g_Q0l; H1=g_Q1h; Lo1=g_Q1l; }
  else if (which == 5) { Ah=g_wkh; Al=g_wkl; Bh=g_xTh;  Bl=g_xTl;
                         M=CCH; N=SP; K=CCH; ns=1; ashare=1; emode=1;
                         H0=g_K0h; Lo0=g_K0l; H1=g_K1h; Lo1=g_K1l; }
  else                 { Ah=g_wvh; Al=g_wvl; Bh=g_xTh;  Bl=g_xTl;  Cd=g_v;
                         M=CCH; N=SP; K=CCH; ns=1; ashare=1; }

  int z = blockIdx.z;
  int b = z / ns, sp = z - b*ns;
  int Kc = K / ns;
  size_t aoff = (ashare ? 0 : (size_t)b*M*K) + (size_t)sp*Kc;
  size_t boff = (size_t)b*N*K + (size_t)sp*Kc;
  int row0 = blockIdx.y*128, col0 = blockIdx.x*128;
  int tid = threadIdx.x, lane = tid&31, wid = tid>>5;
  int wm = (wid&1)*64, wn = (wid>>1)*32;
  int lr = tid>>1, lc8 = (tid&1)*16;
  const __nv_bfloat16* Ahp = Ah + aoff + (size_t)(row0+lr)*K + lc8;
  const __nv_bfloat16* Alp = Al + aoff + (size_t)(row0+lr)*K + lc8;
  const __nv_bfloat16* Bhp = Bh + boff + (size_t)(col0+lr)*K + lc8;
  const __nv_bfloat16* Blp = Bl + boff + (size_t)(col0+lr)*K + lc8;
  unsigned sbase = (unsigned)__cvta_generic_to_shared(smp);
  unsigned rofs = (unsigned)((lr*PADC + lc8)*2);   // 80B row stride -> 16B aligned
  float c[4][4][4] = {};
  int nkb = Kc/32;

  // prefetch k-block 0 into stage 0
  CP16(sbase + rofs,            Ahp);  CP16(sbase + rofs + 16,            Ahp + 8);
  CP16(sbase + TILE_B + rofs,   Alp);  CP16(sbase + TILE_B + rofs + 16,   Alp + 8);
  CP16(sbase + 2*TILE_B + rofs, Bhp);  CP16(sbase + 2*TILE_B + rofs + 16, Bhp + 8);
  CP16(sbase + 3*TILE_B + rofs, Blp);  CP16(sbase + 3*TILE_B + rofs + 16, Blp + 8);
  CPCOMMIT();

  for (int kb = 0; kb < nkb; kb++) {
    int cur = kb & 1;
    if (kb+1 < nkb) {
      unsigned st = sbase + (unsigned)((cur^1)*STAGE_B);
      int o = (kb+1)*32;
      CP16(st + rofs,            Ahp + o);  CP16(st + rofs + 16,            Ahp + o + 8);
      CP16(st + TILE_B + rofs,   Alp + o);  CP16(st + TILE_B + rofs + 16,   Alp + o + 8);
      CP16(st + 2*TILE_B + rofs, Bhp + o);  CP16(st + 2*TILE_B + rofs + 16, Bhp + o + 8);
      CP16(st + 3*TILE_B + rofs, Blp + o);  CP16(st + 3*TILE_B + rofs + 16, Blp + o + 8);
      CPCOMMIT();
      CPWAIT1();
    } else {
      CPWAIT0();
    }
    __syncthreads();
    const __nv_bfloat16* Ahs = smp + cur*STAGE_E;
    const __nv_bfloat16* Als = Ahs + TILE_E;
    const __nv_bfloat16* Bhs = Ahs + 2*TILE_E;
    const __nv_bfloat16* Bls = Ahs + 3*TILE_E;
    #pragma unroll
    for (int ks = 0; ks < 2; ks++) {
      int kk = ks*16 + (lane&3)*2;
      unsigned af[4][4], bfh[4][2], bfl[4][2];
      #pragma unroll
      for (int mi = 0; mi < 4; mi++) {
        int r = wm + mi*16 + (lane>>2);
        af[mi][0] = *(const unsigned*)&Ahs[r*PADC + kk];
        af[mi][1] = *(const unsigned*)&Ahs[(r+8)*PADC + kk];
        af[mi][2] = *(const unsigned*)&Ahs[r*PADC + kk+8];
        af[mi][3] = *(const unsigned*)&Ahs[(r+8)*PADC + kk+8];
      }
      #pragma unroll
      for (int ni = 0; ni < 4; ni++) {
        int nn = wn + ni*8 + (lane>>2);
        bfh[ni][0] = *(const unsigned*)&Bhs[nn*PADC + kk];
        bfh[ni][1] = *(const unsigned*)&Bhs[nn*PADC + kk+8];
        bfl[ni][0] = *(const unsigned*)&Bls[nn*PADC + kk];
        bfl[ni][1] = *(const unsigned*)&Bls[nn*PADC + kk+8];
      }
      #pragma unroll
      for (int mi = 0; mi < 4; mi++)
        #pragma unroll
        for (int ni = 0; ni < 4; ni++) {
          MMA_BF16(c[mi][ni], af[mi], bfh[ni]);
          MMA_BF16(c[mi][ni], af[mi], bfl[ni]);
        }
      #pragma unroll
      for (int mi = 0; mi < 4; mi++) {
        int r = wm + mi*16 + (lane>>2);
        af[mi][0] = *(const unsigned*)&Als[r*PADC + kk];
        af[mi][1] = *(const unsigned*)&Als[(r+8)*PADC + kk];
        af[mi][2] = *(const unsigned*)&Als[r*PADC + kk+8];
        af[mi][3] = *(const unsigned*)&Als[(r+8)*PADC + kk+8];
      }
      #pragma unroll
      for (int mi = 0; mi < 4; mi++)
        #pragma unroll
        for (int ni = 0; ni < 4; ni++)
          MMA_BF16(c[mi][ni], af[mi], bfh[ni]);
    }
    __syncthreads();
  }

  if (emode == 0) {
    float* Co;
    if (ns > 1) Co = Cp + ((size_t)sp*BATCH + b)*M*N;
    else        Co = Cd + (size_t)b*M*N;
    #pragma unroll
    for (int mi = 0; mi < 4; mi++) {
      int r = row0 + wm + mi*16 + (lane>>2);
      float b0 = bias ? bias[r]   : 0.f;
      float b1 = bias ? bias[r+8] : 0.f;
      #pragma unroll
      for (int ni = 0; ni < 4; ni++) {
        int cc = col0 + wn + ni*8 + (lane&3)*2;
        float2 v0 = make_float2(c[mi][ni][0]*scl + b0, c[mi][ni][1]*scl + b0);
        float2 v1 = make_float2(c[mi][ni][2]*scl + b1, c[mi][ni][3]*scl + b1);
        *(float2*)&Co[(size_t)r*N + cc]     = v0;
        *(float2*)&Co[(size_t)(r+8)*N + cc] = v1;
      }
    }
  } else if (emode == 1) {
    int bb = z >> 3, tt = z & 7;
    #pragma unroll
    for (int mi = 0; mi < 4; mi++) {
      int r = wm + mi*16 + (lane>>2);
      float b0 = bias[r], b1 = bias[r+8];
      #pragma unroll
      for (int ni = 0; ni < 4; ni++) {
        int cc = col0 + wn + ni*8 + (lane&3)*2;
        qk_scat2(bb, tt, r,   cc, c[mi][ni][0] + b0, c[mi][ni][1] + b0, H0, Lo0, H1, Lo1);
        qk_scat2(bb, tt, r+8, cc, c[mi][ni][2] + b1, c[mi][ni][3] + b1, H0, Lo0, H1, Lo1);
      }
    }
  } else {
    int sc1 = (emode == 3);
    #pragma unroll
    for (int mi = 0; mi < 4; mi++) {
      int r = row0 + wm + mi*16 + (lane>>2);
      #pragma unroll
      for (int ni = 0; ni < 4; ni++) {
        int cc = col0 + wn + ni*8 + (lane&3)*2;
        pv_scat2(b, r,   cc, c[mi][ni][0], c[mi][ni][1], sc1);
        pv_scat2(b, r+8, cc, c[mi][ni][2], c[mi][ni][3], sc1);
      }
    }
  }
}

// ---------------- 9: fused 3-head masked softmax (fast exp; scale1 sums split-K partials) ----------------
__device__ __forceinline__ float warp_max_(float v){
  #pragma unroll
  for (int o = 16; o; o >>= 1) v = fmaxf(v, __shfl_xor_sync(0xffffffffu, v, o));
  return v;
}
__device__ __forceinline__ float warp_sum_(float v){
  #pragma unroll
  for (int o = 16; o; o >>= 1) v += __shfl_xor_sync(0xffffffffu, v, o);
  return v;
}

__global__ void k_softmax(int scale)
{
  extern __shared__ float sv[];      // 3*L
  __shared__ float rbuf[3][8];
  int L = scale? L1:L0;
  const float* mk = (scale? g_mask1 : g_mask0) + (size_t)blockIdx.y*L;
  const float* sg = (scale? g_sig1  : g_sig0)  + (size_t)blockIdx.y*3*L;
  size_t rowoff = ((size_t)blockIdx.y*L + blockIdx.x)*L;
  const float* row0p = g_S0 + rowoff;
  const float* p1 = g_S1p + (size_t)blockIdx.y*L1*L1 + (size_t)blockIdx.x*L1;
  const size_t PS = (size_t)BATCH*L1*L1;
  __nv_bfloat16* Ph = scale? g_P1h : g_P0h;
  __nv_bfloat16* Pl = scale? g_P1l : g_P0l;
  int tid = threadIdx.x, lane = tid&31, wid = tid>>5;

  float m0 = -3e38f, m1 = -3e38f, m2 = -3e38f;
  for (int k = tid; k < L; k += 256) {
    float s;
    if (scale) s = (p1[k] + p1[k+PS] + p1[k+2*PS] + p1[k+3*PS]) * 0.015625f;
    else       s = row0p[k];
    float v0, v1, v2;
    if (mk[k] > 0.5f) { v0 = v1 = v2 = -1e9f; }
    else { v0 = s*sg[k]; v1 = s*sg[L+k]; v2 = s*sg[2*L+k]; }
    sv[k] = v0; sv[L+k] = v1; sv[2*L+k] = v2;
    m0 = fmaxf(m0, v0); m1 = fmaxf(m1, v1); m2 = fmaxf(m2, v2);
  }
  m0 = warp_max_(m0); m1 = warp_max_(m1); m2 = warp_max_(m2);
  if (lane == 0) { rbuf[0][wid]=m0; rbuf[1][wid]=m1; rbuf[2][wid]=m2; }
  __syncthreads();
  m0 = rbuf[0][0]; m1 = rbuf[1][0]; m2 = rbuf[2][0];
  #pragma unroll
  for (int w = 1; w < 8; w++) {
    m0 = fmaxf(m0, rbuf[0][w]); m1 = fmaxf(m1, rbuf[1][w]); m2 = fmaxf(m2, rbuf[2][w]);
  }
  __syncthreads();

  float z0 = 0.f, z1 = 0.f, z2 = 0.f;
  for (int k = tid; k < L; k += 256) {
    float e0 = fexp_(sv[k]     - m0);
    float e1 = fexp_(sv[L+k]   - m1);
    float e2 = fexp_(sv[2*L+k] - m2);
    sv[k] = e0; sv[L+k] = e1; sv[2*L+k] = e2;
    z0 += e0; z1 += e1; z2 += e2;
  }
  z0 = warp_sum_(z0); z1 = warp_sum_(z1); z2 = warp_sum_(z2);
  if (lane == 0) { rbuf[0][wid]=z0; rbuf[1][wid]=z1; rbuf[2][wid]=z2; }
  __syncthreads();
  z0 = 0.f; z1 = 0.f; z2 = 0.f;
  #pragma unroll
  for (int w = 0; w < 8; w++) { z0 += rbuf[0][w]; z1 += rbuf[1][w]; z2 += rbuf[2][w]; }
  float i0 = 1.f/(3.f*z0), i1 = 1.f/(3.f*z1), i2 = 1.f/(3.f*z2);
  for (int k = tid; k < L; k += 256) {
    float p = sv[k]*i0 + sv[L+k]*i1 + sv[2*L+k]*i2;
    split_(p, Ph, Pl, (int)(rowoff + k));
  }
}

// ---------------- 12: wo 3x3 conv, single-pass fused hi/lo implicit GEMM (2 CTA/SM) ----------------
__global__ void __launch_bounds__(256,2) k_conv_mma(
    const float* __restrict__ bo, float* __restrict__ out)
{
  __shared__ __align__(16) __nv_bfloat16 Ahs[128][40];
  __shared__ __align__(16) __nv_bfloat16 Als[128][40];
  __shared__ __align__(16) __nv_bfloat16 Bhs[128][40];
  __shared__ __align__(16) __nv_bfloat16 Bls[128][40];
  int n = blockIdx.z;
  int col0 = blockIdx.x*128;
  int tid = threadIdx.x, lane = tid&31, wid = tid>>5;
  int wm = (wid&1)*64, wn = (wid>>1)*32;
  int lr = tid>>1, lc = (tid&1)*16;
  int nloc = tid & 127, khalf = tid >> 7;
  int pos = col0 + nloc;
  int py = pos >> 6, px = pos & 63;
  const __nv_bfloat16* Bph = g_attnh + (size_t)n*PLANE;
  const __nv_bfloat16* Bpl = g_attnl + (size_t)n*PLANE;
  float c[4][4][4] = {};
  #pragma unroll 1
  for (int kb = 0; kb < 36; kb++) {
    __syncthreads();
    *(float4*)&Ahs[lr][lc]   = *(const float4*)(g_woh + (size_t)lr*1152 + kb*32 + lc);
    *(float4*)&Ahs[lr][lc+8] = *(const float4*)(g_woh + (size_t)lr*1152 + kb*32 + lc + 8);
    *(float4*)&Als[lr][lc]   = *(const float4*)(g_wol + (size_t)lr*1152 + kb*32 + lc);
    *(float4*)&Als[lr][lc+8] = *(const float4*)(g_wol + (size_t)lr*1152 + kb*32 + lc + 8);
    #pragma unroll
    for (int u = 0; u < 16; u++) {
      int k = kb*32 + khalf*16 + u;
      int ic = k/9;
      int rr = k - ic*9;
      int ky = rr/3 - 1, kx = rr - (rr/3)*3 - 1;
      int iy = py + ky, ix = px + kx;
      __nv_bfloat16 vh = __float2bfloat16(0.f), vl = vh;
      if ((unsigned)iy < 64u && (unsigned)ix < 64u) {
        size_t o = (size_t)ic*SP + iy*64 + ix;
        vh = Bph[o]; vl = Bpl[o];
      }
      Bhs[nloc][khalf*16 + u] = vh;
      Bls[nloc][khalf*16 + u] = vl;
    }
    __syncthreads();
    #pragma unroll
    for (int ks = 0; ks < 2; ks++) {
      int kk = ks*16 + (lane&3)*2;
      unsigned af[4][4], bfh[4][2], bfl[4][2];
      #pragma unroll
      for (int mi = 0; mi < 4; mi++) {
        int r = wm + mi*16 + (lane>>2);
        af[mi][0] = *(const unsigned*)&Ahs[r][kk];
        af[mi][1] = *(const unsigned*)&Ahs[r+8][kk];
        af[mi][2] = *(const unsigned*)&Ahs[r][kk+8];
        af[mi][3] = *(const unsigned*)&Ahs[r+8][kk+8];
      }
      #pragma unroll
      for (int ni = 0; ni < 4; ni++) {
        int nn = wn + ni*8 + (lane>>2);
        bfh[ni][0] = *(const unsigned*)&Bhs[nn][kk];
        bfh[ni][1] = *(const unsigned*)&Bhs[nn][kk+8];
        bfl[ni][0] = *(const unsigned*)&Bls[nn][kk];
        bfl[ni][1] = *(const unsigned*)&Bls[nn][kk+8];
      }
      #pragma unroll
      for (int mi = 0; mi < 4; mi++)
        #pragma unroll
        for (int ni = 0; ni < 4; ni++) {
          MMA_BF16(c[mi][ni], af[mi], bfh[ni]);
          MMA_BF16(c[mi][ni], af[mi], bfl[ni]);
        }
      #pragma unroll
      for (int mi = 0; mi < 4; mi++) {
        int r = wm + mi*16 + (lane>>2);
        af[mi][0] = *(const unsigned*)&Als[r][kk];
        af[mi][1] = *(const unsigned*)&Als[r+8][kk];
        af[mi][2] = *(const unsigned*)&Als[r][kk+8];
        af[mi][3] = *(const unsigned*)&Als[r+8][kk+8];
      }
      #pragma unroll
      for (int mi = 0; mi < 4; mi++)
        #pragma unroll
        for (int ni = 0; ni < 4; ni++)
          MMA_BF16(c[mi][ni], af[mi], bfh[ni]);
    }
  }
  #pragma unroll
  for (int mi = 0; mi < 4; mi++) {
    int r = wm + mi*16 + (lane>>2);
    float b0 = bo[r], b1 = bo[r+8];
    #pragma unroll
    for (int ni = 0; ni < 4; ni++) {
      int cc = col0 + wn + ni*8 + (lane&3)*2;
      float v0 = c[mi][ni][0] + b0, v1 = c[mi][ni][1] + b0;
      float v2 = c[mi][ni][2] + b1, v3 = c[mi][ni][3] + b1;
      v0 = (v0 >= 0.f) ? v0 : 0.2f*v0;
      v1 = (v1 >= 0.f) ? v1 : 0.2f*v1;
      v2 = (v2 >= 0.f) ? v2 : 0.2f*v2;
      v3 = (v3 >= 0.f) ? v3 : 0.2f*v3;
      *(float2*)&out[(size_t)n*PLANE + (size_t)r*SP + cc]     = make_float2(v0, v1);
      *(float2*)&out[(size_t)n*PLANE + (size_t)(r+8)*SP + cc] = make_float2(v2, v3);
    }
  }
}

// ---------------- host ----------------
extern "C" void kernel_launch(void* const* d_in, const int* in_sizes, int n_in,
                              void* d_out, int out_size)
{
  const float* x     = (const float*)d_in[0];
  const float* m     = (const float*)d_in[1];
  const float* dmap  = (const float*)d_in[2];
  const float* wq    = (const float*)d_in[3];
  const float* bq    = (const float*)d_in[4];
  const float* wk    = (const float*)d_in[5];
  const float* bk    = (const float*)d_in[6];
  const float* wv    = (const float*)d_in[7];
  const float* bv    = (const float*)d_in[8];
  const float* wvle  = (const float*)d_in[9];
  const float* bvle  = (const float*)d_in[10];
  const float* wd1   = (const float*)d_in[11];
  const float* bd1   = (const float*)d_in[12];
  const float* wd2   = (const float*)d_in[13];
  const float* bd2   = (const float*)d_in[14];
  const float* wo    = (const float*)d_in[15];
  const float* bo    = (const float*)d_in[16];
  float* out = (float*)d_out;

  cudaFuncSetAttribute(k_gemm_nt, cudaFuncAttributeMaxDynamicSharedMemorySize, GEMM_SMEM);

  k_xprep<<<dim3(128,4,16), 256>>>(x);
  k_wprep<<<(CCH*1152 + 3*CCH*CCH + 255)/256, 256>>>(wo, wq, wk, wv);

  k_gemm_nt<<<dim3(SP/128, 1, BT), 256, GEMM_SMEM>>>(4, bq);
  k_gemm_nt<<<dim3(SP/128, 1, BT), 256, GEMM_SMEM>>>(5, bk);
  k_gemm_nt<<<dim3(SP/128, 1, BT), 256, GEMM_SMEM>>>(6, bv);

  k_vle<<<(BT*PLANE)/256, 256>>>(x, wvle, bvle);
  k_depth<<<dim3(16,16), 256>>>(dmap, wd1, bd1, wd2, bd2);

  k_patch_vt<<<(2*L0*D0)/256, 256>>>(0);
  k_patch_vt<<<(2*L1*D1)/256, 256>>>(1);
  k_stats<<<(2*L0+255)/256, 256>>>(m, 0);
  k_stats<<<(2*L1+255)/256, 256>>>(m, 1);

  k_gemm_nt<<<dim3(L0/128, L0/128, BATCH), 256, GEMM_SMEM>>>(0, nullptr);
  k_gemm_nt<<<dim3(L1/128, L1/128, BATCH*NS1), 256, GEMM_SMEM>>>(1, nullptr);

  k_softmax<<<dim3(L0, BATCH), 256, 3*L0*sizeof(float)>>>(0);
  k_softmax<<<dim3(L1, BATCH), 256, 3*L1*sizeof(float)>>>(1);

  k_gemm_nt<<<dim3(D0/128, L0/128, BATCH), 256, GEMM_SMEM>>>(2, nullptr);
  k_gemm_nt<<<dim3(D1/128, L1/128, BATCH), 256, GEMM_SMEM>>>(3, nullptr);

  k_conv_mma<<<dim3(32,1,16), 256>>>(bo, out);

  cudaMemcpyAsync(out + BT*PLANE, dmap, (size_t)BT*65536*sizeof(float),
                  cudaMemcpyDeviceToDevice);
}